// round 4
// baseline (speedup 1.0000x reference)
#include <cuda_runtime.h>
#include <cuda_bf16.h>
#include <math.h>
#include <stdint.h>

#define BATCH 2
#define SEQ   2048
#define DM    512
#define HD    64
#define ROWS  (BATCH*SEQ)
#define SCALE 0.125f
#define EPS   1e-5f

typedef __nv_bfloat16  bf16;
typedef __nv_bfloat162 bf162;

// ---------------- scratch ----------------
__device__ bf16  g_xnh[ROWS*DM];
__device__ bf16  g_qh [ROWS*DM], g_kh[ROWS*DM], g_vh[ROWS*DM];
__device__ bf16  g_ah [ROWS*DM];                       // attention out (Wo input)
__device__ bf16  g_wqh[DM*DM], g_wkh[DM*DM], g_wvh[DM*DM], g_woh[DM*DM], g_w1h[DM*DM];
__device__ float g_t1 [ROWS*DM];
__device__ float g_proj[ROWS*DM];
__device__ float g_tl [ROWS];
__device__ bf16  g_sb [4L*SEQ*SEQ];                    // scores (2 global heads x 2 batches)
__device__ bf16  g_ph [4L*SEQ*SEQ];                    // probs
__device__ bf16  g_vth[4L*HD*SEQ];                     // V transposed per global head

// ---------------- helpers ----------------
__device__ __forceinline__ void cpa16(void* dst, const void* src){
    uint32_t d = (uint32_t)__cvta_generic_to_shared(dst);
    asm volatile("cp.async.cg.shared.global [%0], [%1], 16;\n" :: "r"(d), "l"(src));
}
#define CP_COMMIT() asm volatile("cp.async.commit_group;\n" ::: "memory")
#define CP_WAIT0()  asm volatile("cp.async.wait_group 0;\n" ::: "memory")
#define CP_WAIT1()  asm volatile("cp.async.wait_group 1;\n" ::: "memory")

#define MMA_BF16(d, a, b) \
    asm volatile("mma.sync.aligned.m16n8k16.row.col.f32.bf16.bf16.f32 " \
        "{%0,%1,%2,%3},{%4,%5,%6,%7},{%8,%9},{%0,%1,%2,%3};" \
        : "+f"((d)[0]), "+f"((d)[1]), "+f"((d)[2]), "+f"((d)[3]) \
        : "r"((a)[0]), "r"((a)[1]), "r"((a)[2]), "r"((a)[3]), "r"((b)[0]), "r"((b)[1]))

__device__ __forceinline__ float warp_red_sum(float v){
#pragma unroll
    for (int o=16;o;o>>=1) v += __shfl_xor_sync(0xffffffffu, v, o);
    return v;
}
__device__ __forceinline__ float warp_red_max(float v){
#pragma unroll
    for (int o=16;o;o>>=1) v = fmaxf(v, __shfl_xor_sync(0xffffffffu, v, o));
    return v;
}
__device__ float block_red_sum(float v, float* sh){
    __syncthreads();
    int lane = threadIdx.x & 31, wid = threadIdx.x >> 5;
    v = warp_red_sum(v);
    if (lane==0) sh[wid] = v;
    __syncthreads();
    int nw = (blockDim.x + 31) >> 5;
    float r = (threadIdx.x < nw) ? sh[threadIdx.x] : 0.f;
    r = warp_red_sum(r);
    if (threadIdx.x==0) sh[0] = r;
    __syncthreads();
    return sh[0];
}
__device__ float block_red_max(float v, float* sh){
    __syncthreads();
    int lane = threadIdx.x & 31, wid = threadIdx.x >> 5;
    v = warp_red_max(v);
    if (lane==0) sh[wid] = v;
    __syncthreads();
    int nw = (blockDim.x + 31) >> 5;
    float r = (threadIdx.x < nw) ? sh[threadIdx.x] : -1e30f;
    r = warp_red_max(r);
    if (threadIdx.x==0) sh[0] = r;
    __syncthreads();
    return sh[0];
}

// ---------------- input layernorm -> bf16 ----------------
__global__ void ln_bf16(const float* __restrict__ x, const float* __restrict__ g,
                        const float* __restrict__ b, bf16* __restrict__ o){
    __shared__ float sh[33];
    int row = blockIdx.x;
    const float* xr = x + (long)row*DM;
    float s=0.f, s2=0.f;
    for (int d=threadIdx.x; d<DM; d+=blockDim.x){ float v=xr[d]; s+=v; s2+=v*v; }
    s  = block_red_sum(s,  sh);
    s2 = block_red_sum(s2, sh);
    float mu  = s * (1.0f/DM);
    float var = s2 * (1.0f/DM) - mu*mu;
    float inv = rsqrtf(var + EPS);
    for (int d=threadIdx.x; d<DM; d+=blockDim.x)
        o[(long)row*DM + d] = __float2bfloat16((xr[d]-mu)*inv*g[d] + b[d]);
}

// ---------------- weight converts (5 matrices, one launch) ----------------
__global__ void cvtw(const float* w0,const float* w1,const float* w2,const float* w3,const float* w4,
                     bf16* o0, bf16* o1, bf16* o2, bf16* o3, bf16* o4){
    const float* w; bf16* o;
    switch (blockIdx.y){
        case 0: w=w0; o=o0; break;
        case 1: w=w1; o=o1; break;
        case 2: w=w2; o=o2; break;
        case 3: w=w3; o=o3; break;
        default:w=w4; o=o4; break;
    }
    for (int i = blockIdx.x*blockDim.x + threadIdx.x; i < DM*DM; i += gridDim.x*blockDim.x)
        o[i] = __float2bfloat16(w[i]);
}

// ---------------- fused QKV + tanh-MLP projection GEMM (z selects) ----------
// C[4096,512] = xn @ W^T.  z=0..2 -> bf16 out (qh/kh/vh); z=3 -> t1 = tanh(.+bias)
__global__ void __launch_bounds__(256) proj_gemm(
    const bf16* __restrict__ A,
    const bf16* __restrict__ BWq, const bf16* __restrict__ BWk,
    const bf16* __restrict__ BWv, const bf16* __restrict__ BW1,
    bf16* __restrict__ Cq, bf16* __restrict__ Ck, bf16* __restrict__ Cv,
    float* __restrict__ Ct, const float* __restrict__ bias)
{
    constexpr int BM=128, BN=128, WM=4, WN=2;
    constexpr int WTM=BM/WM, WTN=BN/WN, MF=WTM/16, NF=WTN/8, KS=40;
    __shared__ bf16 sA[2][BM*KS], sB[2][BN*KS];
    const int tid = threadIdx.x, wid = tid>>5, lane = tid&31;
    const int wm = wid%WM, wn = wid/WM, g = lane>>2, tg = lane&3;
    const int z = blockIdx.z;
    const bf16* B = (z==0)?BWq : (z==1)?BWk : (z==2)?BWv : BW1;
    const int m0 = blockIdx.y*BM, n0 = blockIdx.x*BN;

    float acc[MF][NF][4];
#pragma unroll
    for (int i=0;i<MF;i++)
#pragma unroll
        for (int j=0;j<NF;j++)
#pragma unroll
            for (int t=0;t<4;t++) acc[i][j][t]=0.f;

    const int NC = DM>>5;
    // prologue stage 0
#pragma unroll
    for (int i=tid;i<BM*4;i+=256){int r=i>>2,c=i&3; cpa16(&sA[0][r*KS+c*8], A+(long)(m0+r)*DM+c*8);}
#pragma unroll
    for (int i=tid;i<BN*4;i+=256){int r=i>>2,c=i&3; cpa16(&sB[0][r*KS+c*8], B+(long)(n0+r)*DM+c*8);}
    CP_COMMIT();

    for (int c=0;c<NC;c++){
        if (c+1<NC){
            int k0=(c+1)<<5, st=(c+1)&1;
#pragma unroll
            for (int i=tid;i<BM*4;i+=256){int r=i>>2,cc=i&3; cpa16(&sA[st][r*KS+cc*8], A+(long)(m0+r)*DM+k0+cc*8);}
#pragma unroll
            for (int i=tid;i<BN*4;i+=256){int r=i>>2,cc=i&3; cpa16(&sB[st][r*KS+cc*8], B+(long)(n0+r)*DM+k0+cc*8);}
            CP_COMMIT();
            CP_WAIT1();
        } else CP_WAIT0();
        __syncthreads();
        const bf16* pA=sA[c&1]; const bf16* pB=sB[c&1];
#pragma unroll
        for (int ks=0; ks<32; ks+=16){
            const int kr = ks + tg*2;
            uint32_t a[MF][4], b[NF][2];
#pragma unroll
            for (int mf=0;mf<MF;mf++){
                int ar = wm*WTM + mf*16 + g;
                a[mf][0]=*(const uint32_t*)&pA[ ar   *KS+kr  ];
                a[mf][1]=*(const uint32_t*)&pA[(ar+8)*KS+kr  ];
                a[mf][2]=*(const uint32_t*)&pA[ ar   *KS+kr+8];
                a[mf][3]=*(const uint32_t*)&pA[(ar+8)*KS+kr+8];
            }
#pragma unroll
            for (int nf=0;nf<NF;nf++){
                int br = wn*WTN + nf*8 + g;
                b[nf][0]=*(const uint32_t*)&pB[br*KS+kr  ];
                b[nf][1]=*(const uint32_t*)&pB[br*KS+kr+8];
            }
#pragma unroll
            for (int mf=0;mf<MF;mf++)
#pragma unroll
                for (int nf=0;nf<NF;nf++)
                    MMA_BF16(acc[mf][nf], a[mf], b[nf]);
        }
        __syncthreads();
    }

    bf16* Cb = (z==0)?Cq : (z==1)?Ck : Cv;
#pragma unroll
    for (int mf=0;mf<MF;mf++){
#pragma unroll
        for (int half=0;half<2;half++){
            long row = m0 + wm*WTM + mf*16 + g + half*8;
#pragma unroll
            for (int nf=0;nf<NF;nf++){
                int col = n0 + wn*WTN + nf*8 + tg*2;
                float v0 = acc[mf][nf][half*2+0];
                float v1 = acc[mf][nf][half*2+1];
                long base = row*(long)DM + col;
                if (z==3){
                    v0 = tanhf(v0 + bias[col]);
                    v1 = tanhf(v1 + bias[col+1]);
                    *(float2*)(Ct + base) = make_float2(v0, v1);
                } else {
                    *(bf162*)(Cb + base) = __floats2bfloat162_rn(v0, v1);
                }
            }
        }
    }
}

// ---------------- generic single-product HMMA GEMM ----------------
// C[M,N] = A[M,K] @ B[N,K]^T.  EPI 0: fp32 C.  EPI 3: bf16 Cb.
template<int BM,int BN,int WM,int WN,int EPI>
__global__ void __launch_bounds__(256) hmma_gemm(
    const bf16* __restrict__ A, const bf16* __restrict__ B,
    float* __restrict__ C, bf16* __restrict__ Cb,
    int K, int lda, int ldb, int ldc,
    long oAh, long oAl, long oBh, long oBl, long oCh, long oCl)
{
    constexpr int WTM=BM/WM, WTN=BN/WN, MF=WTM/16, NF=WTN/8, KS=40;
    __shared__ bf16 sA[2][BM*KS], sB[2][BN*KS];
    const int tid = threadIdx.x, wid = tid>>5, lane = tid&31;
    const int wm = wid%WM, wn = wid/WM, g = lane>>2, tg = lane&3;
    const int z = blockIdx.z, zh = z>>1, zl = z&1;
    A += zh*oAh + zl*oAl;  B += zh*oBh + zl*oBl;
    const long co = zh*oCh + zl*oCl;
    const int m0 = blockIdx.y*BM, n0 = blockIdx.x*BN;

    float acc[MF][NF][4];
#pragma unroll
    for (int i=0;i<MF;i++)
#pragma unroll
        for (int j=0;j<NF;j++)
#pragma unroll
            for (int t=0;t<4;t++) acc[i][j][t]=0.f;

    const int NC = K>>5;
#pragma unroll
    for (int i=tid;i<BM*4;i+=256){int r=i>>2,c=i&3; cpa16(&sA[0][r*KS+c*8], A+(long)(m0+r)*lda+c*8);}
#pragma unroll
    for (int i=tid;i<BN*4;i+=256){int r=i>>2,c=i&3; cpa16(&sB[0][r*KS+c*8], B+(long)(n0+r)*ldb+c*8);}
    CP_COMMIT();

    for (int c=0;c<NC;c++){
        if (c+1<NC){
            int k0=(c+1)<<5, st=(c+1)&1;
#pragma unroll
            for (int i=tid;i<BM*4;i+=256){int r=i>>2,cc=i&3; cpa16(&sA[st][r*KS+cc*8], A+(long)(m0+r)*lda+k0+cc*8);}
#pragma unroll
            for (int i=tid;i<BN*4;i+=256){int r=i>>2,cc=i&3; cpa16(&sB[st][r*KS+cc*8], B+(long)(n0+r)*ldb+k0+cc*8);}
            CP_COMMIT();
            CP_WAIT1();
        } else CP_WAIT0();
        __syncthreads();
        const bf16* pA=sA[c&1]; const bf16* pB=sB[c&1];
#pragma unroll
        for (int ks=0; ks<32; ks+=16){
            const int kr = ks + tg*2;
            uint32_t a[MF][4], b[NF][2];
#pragma unroll
            for (int mf=0;mf<MF;mf++){
                int ar = wm*WTM + mf*16 + g;
                a[mf][0]=*(const uint32_t*)&pA[ ar   *KS+kr  ];
                a[mf][1]=*(const uint32_t*)&pA[(ar+8)*KS+kr  ];
                a[mf][2]=*(const uint32_t*)&pA[ ar   *KS+kr+8];
                a[mf][3]=*(const uint32_t*)&pA[(ar+8)*KS+kr+8];
            }
#pragma unroll
            for (int nf=0;nf<NF;nf++){
                int br = wn*WTN + nf*8 + g;
                b[nf][0]=*(const uint32_t*)&pB[br*KS+kr  ];
                b[nf][1]=*(const uint32_t*)&pB[br*KS+kr+8];
            }
#pragma unroll
            for (int mf=0;mf<MF;mf++)
#pragma unroll
                for (int nf=0;nf<NF;nf++)
                    MMA_BF16(acc[mf][nf], a[mf], b[nf]);
        }
        __syncthreads();
    }

#pragma unroll
    for (int mf=0;mf<MF;mf++){
#pragma unroll
        for (int half=0;half<2;half++){
            long row = m0 + wm*WTM + mf*16 + g + half*8;
#pragma unroll
            for (int nf=0;nf<NF;nf++){
                int col = n0 + wn*WTN + nf*8 + tg*2;
                float v0 = acc[mf][nf][half*2+0];
                float v1 = acc[mf][nf][half*2+1];
                long base = co + row*(long)ldc + col;
                if (EPI == 0)
                    *(float2*)(C + base) = make_float2(v0, v1);
                else
                    *(bf162*)(Cb + base) = __floats2bfloat162_rn(v0, v1);
            }
        }
    }
}

// ---------------- softmax bf16 -> bf16 (global heads) ----------------
__global__ void softmax_bf16(const bf16* __restrict__ S, bf16* __restrict__ P){
    __shared__ float sh[33];
    long base = (long)blockIdx.y*SEQ*SEQ + (long)blockIdx.x*SEQ;
    const bf162* row = (const bf162*)(S + base);
    float2 v[4]; float m = -1e30f;
#pragma unroll
    for (int i=0;i<4;i++){
        v[i] = __bfloat1622float2(row[threadIdx.x + i*256]);
        m = fmaxf(m, fmaxf(v[i].x, v[i].y));
    }
    m = block_red_max(m, sh);
    float sum = 0.f;
#pragma unroll
    for (int i=0;i<4;i++){
        v[i].x = __expf((v[i].x - m)*SCALE);
        v[i].y = __expf((v[i].y - m)*SCALE);
        sum += v[i].x + v[i].y;
    }
    sum = block_red_sum(sum, sh);
    float inv = 1.0f/sum;
    bf162* out = (bf162*)(P + base);
#pragma unroll
    for (int i=0;i<4;i++)
        out[threadIdx.x + i*256] = __floats2bfloat162_rn(v[i].x*inv, v[i].y*inv);
}

// ---------------- V transpose (global heads) ----------------
__global__ void vtrans(const bf16* __restrict__ v, bf16* __restrict__ vt){
    __shared__ bf16 t[32][33];
    int z = blockIdx.z, b = z>>1, h = z&1;
    int k0 = blockIdx.x*32, n0 = blockIdx.y*32;
    for (int i = threadIdx.y; i < 32; i += 8)
        t[i][threadIdx.x] = v[(long)(b*SEQ + k0 + i)*DM + h*HD + n0 + threadIdx.x];
    __syncthreads();
    for (int i = threadIdx.y; i < 32; i += 8)
        vt[(long)z*HD*SEQ + (long)(n0+i)*SEQ + k0 + threadIdx.x] = t[threadIdx.x][i];
}

// ---------------- sparse heads (bf16 in, bf16 out) ----------------
__global__ void sparse_attn(const bf16* __restrict__ Q, const bf16* __restrict__ Kk,
                            const bf16* __restrict__ V, bf16* __restrict__ O){
    int hy = blockIdx.y;            // 0..5 -> heads 2..7
    int h  = hy + 2;
    int b  = blockIdx.z;
    int wid = threadIdx.x >> 5, lane = threadIdx.x & 31;
    int q = blockIdx.x*4 + wid;

    int w   = (hy==1) ? 128 : (hy==2) ? 256 : 64;
    int dil = (hy<3)  ? 1   : (1 << (hy-2));

    __shared__ float qs[4][64];
    __shared__ float pbuf[4][520];

    const bf16* qrow = Q + ((long)(b*SEQ + q)*DM + h*HD);
    qs[wid][lane]    = __bfloat162float(qrow[lane]);
    qs[wid][lane+32] = __bfloat162float(qrow[lane+32]);
    __syncwarp();

    int jlo = -min(w, q/dil);
    int jhi =  min(w, (SEQ-1-q)/dil);
    int cnt = jhi - jlo + 1;

    const bf16* Kbase = Kk + ((long)b*SEQ*DM + h*HD);
    const bf16* Vbase = V  + ((long)b*SEQ*DM + h*HD);

    float mmax = -1e30f;
    for (int jj=lane; jj<cnt; jj+=32){
        int k = q + (jlo+jj)*dil;
        const bf162* kr2 = (const bf162*)(Kbase + (long)k*DM);
        float s = 0.f;
#pragma unroll
        for (int d=0; d<32; d++){
            float2 f = __bfloat1622float2(kr2[d]);
            s += qs[wid][2*d]*f.x + qs[wid][2*d+1]*f.y;
        }
        s *= SCALE;
        pbuf[wid][jj] = s;
        mmax = fmaxf(mmax, s);
    }
    mmax = warp_red_max(mmax);
    float sum = 0.f;
    for (int jj=lane; jj<cnt; jj+=32){
        float e = __expf(pbuf[wid][jj] - mmax);
        pbuf[wid][jj] = e;
        sum += e;
    }
    sum = warp_red_sum(sum);
    float inv = 1.0f/sum;
    __syncwarp();

    float o0=0.f, o1=0.f;
#pragma unroll 4
    for (int jj=0; jj<cnt; jj++){
        int k = q + (jlo+jj)*dil;
        float p = pbuf[wid][jj];
        const bf16* vr = Vbase + (long)k*DM;
        o0 += p*__bfloat162float(vr[lane]);
        o1 += p*__bfloat162float(vr[lane+32]);
    }
    bf16* orow = O + ((long)(b*SEQ + q)*DM + h*HD);
    orow[lane]    = __float2bfloat16(o0*inv);
    orow[lane+32] = __float2bfloat16(o1*inv);
}

// ---------------- T gate ----------------
__global__ void tdot_kernel(const float* __restrict__ t1, const float* __restrict__ w2,
                            const float* __restrict__ b2, float* __restrict__ tl){
    __shared__ float sh[33];
    int row = blockIdx.x;
    const float* tr = t1 + (long)row*DM;
    float s = 0.f;
    for (int d=threadIdx.x; d<DM; d+=blockDim.x) s += tr[d]*w2[d];
    s = block_red_sum(s, sh);
    if (threadIdx.x==0) tl[row] = s + b2[0];
}
__global__ void tsoftmax_kernel(float* __restrict__ tl){
    __shared__ float sh[33];
    float* p = tl + (long)blockIdx.x*SEQ;
    int tid = threadIdx.x;
    float v0 = p[tid], v1 = p[tid+1024];
    float m = block_red_max(fmaxf(v0,v1), sh);
    float e0 = __expf(v0-m), e1 = __expf(v1-m);
    float s = block_red_sum(e0+e1, sh);
    float inv = 1.0f/s;
    p[tid] = e0*inv; p[tid+1024] = e1*inv;
}

// ---------------- final: gate, residual, output layernorm ----------------
__global__ void final_kernel(const float* __restrict__ proj, const float* __restrict__ x0,
                             const float* __restrict__ tl, const float* __restrict__ g,
                             const float* __restrict__ b, float* __restrict__ out){
    __shared__ float sh[33];
    int row = blockIdx.x;
    float t = tl[row];
    const float* pr = proj + (long)row*DM;
    const float* xr = x0   + (long)row*DM;
    float s=0.f, s2=0.f;
    for (int d=threadIdx.x; d<DM; d+=blockDim.x){
        float v = pr[d]*t + xr[d];
        s += v; s2 += v*v;
    }
    s  = block_red_sum(s,  sh);
    s2 = block_red_sum(s2, sh);
    float mu  = s * (1.0f/DM);
    float var = s2 * (1.0f/DM) - mu*mu;
    float inv = rsqrtf(var + EPS);
    float* o = out + (long)row*DM;
    for (int d=threadIdx.x; d<DM; d+=blockDim.x){
        float v = pr[d]*t + xr[d];
        o[d] = (v-mu)*inv*g[d] + b[d];
    }
}

// ---------------- launcher ----------------
extern "C" void kernel_launch(void* const* d_in, const int* in_sizes, int n_in,
                              void* d_out, int out_size)
{
    const float* x      = (const float*)d_in[0];
    const float* Wq     = (const float*)d_in[1];
    const float* Wk     = (const float*)d_in[2];
    const float* Wv     = (const float*)d_in[3];
    const float* Wo     = (const float*)d_in[4];
    const float* T_w1   = (const float*)d_in[5];
    const float* T_b1   = (const float*)d_in[6];
    const float* T_w2   = (const float*)d_in[7];
    const float* T_b2   = (const float*)d_in[8];
    const float* ln_in_g  = (const float*)d_in[9];
    const float* ln_in_b  = (const float*)d_in[10];
    const float* ln_out_g = (const float*)d_in[11];
    const float* ln_out_b = (const float*)d_in[12];
    float* out = (float*)d_out;

    bf16 *xnh,*qh,*kh,*vh,*ah,*wqh,*wkh,*wvh,*woh,*w1h,*sb,*ph,*vth;
    float *t1,*proj,*tl;
    cudaGetSymbolAddress((void**)&xnh, g_xnh);
    cudaGetSymbolAddress((void**)&qh,  g_qh);
    cudaGetSymbolAddress((void**)&kh,  g_kh);
    cudaGetSymbolAddress((void**)&vh,  g_vh);
    cudaGetSymbolAddress((void**)&ah,  g_ah);
    cudaGetSymbolAddress((void**)&wqh, g_wqh);
    cudaGetSymbolAddress((void**)&wkh, g_wkh);
    cudaGetSymbolAddress((void**)&wvh, g_wvh);
    cudaGetSymbolAddress((void**)&woh, g_woh);
    cudaGetSymbolAddress((void**)&w1h, g_w1h);
    cudaGetSymbolAddress((void**)&sb,  g_sb);
    cudaGetSymbolAddress((void**)&ph,  g_ph);
    cudaGetSymbolAddress((void**)&vth, g_vth);
    cudaGetSymbolAddress((void**)&t1,  g_t1);
    cudaGetSymbolAddress((void**)&proj,g_proj);
    cudaGetSymbolAddress((void**)&tl,  g_tl);

    // 1. input LN -> bf16
    ln_bf16<<<ROWS,128>>>(x, ln_in_g, ln_in_b, xnh);

    // 2. convert all 5 weight matrices (one launch)
    cvtw<<<dim3(64,5),256>>>(Wq,Wk,Wv,Wo,T_w1, wqh,wkh,wvh,woh,w1h);

    // 3. fused Q/K/V/tanh-MLP projections (one launch, z=0..3)
    proj_gemm<<<dim3(DM/128, ROWS/128, 4),256>>>(xnh, wqh,wkh,wvh,w1h,
                                                 qh,kh,vh, t1, T_b1);

    // 4. T gate
    tdot_kernel<<<ROWS,128>>>(t1, T_w2, T_b2, tl);
    tsoftmax_kernel<<<BATCH,1024>>>(tl);

    // 5. global heads: S = Q K^T (bf16 out) ; softmax ; P V -> ah
    hmma_gemm<128,128,4,2,3><<<dim3(SEQ/128, SEQ/128, 4),256>>>(
        qh, kh, nullptr, sb,
        HD, DM, DM, SEQ,
        (long)SEQ*DM, HD, (long)SEQ*DM, HD,
        2L*SEQ*SEQ, (long)SEQ*SEQ);
    softmax_bf16<<<dim3(SEQ,4),256>>>(sb, ph);
    vtrans<<<dim3(SEQ/32, HD/32, 4), dim3(32,8)>>>(vh, vth);
    hmma_gemm<64,64,2,4,3><<<dim3(1, SEQ/64, 4),256>>>(
        ph, vth, nullptr, ah,
        SEQ, SEQ, SEQ, DM,
        2L*SEQ*SEQ, (long)SEQ*SEQ,
        2L*HD*SEQ, (long)HD*SEQ,
        (long)SEQ*DM, HD);

    // 6. sparse heads (h=2..7) -> ah
    sparse_attn<<<dim3(SEQ/4,6,BATCH),128>>>(qh, kh, vh, ah);

    // 7. output projection: proj = ah @ Wo^T
    hmma_gemm<128,128,4,2,0><<<dim3(DM/128, ROWS/128, 1),256>>>(
        ah, woh, proj, nullptr,
        DM, DM, DM, DM, 0,0,0,0,0,0);

    // 8. gate * out + residual + output LN
    final_kernel<<<ROWS,128>>>(proj, x, tl, ln_out_g, ln_out_b, out);
}

// round 5
// speedup vs baseline: 2.0403x; 2.0403x over previous
#include <cuda_runtime.h>
#include <cuda_bf16.h>
#include <math.h>
#include <stdint.h>

#define BATCH 2
#define SEQ   2048
#define DM    512
#define HD    64
#define ROWS  (BATCH*SEQ)
#define SCALE 0.125f
#define EPS   1e-5f

typedef __nv_bfloat16  bf16;
typedef __nv_bfloat162 bf162;

// ---------------- scratch ----------------
__device__ bf16  g_xnh[ROWS*DM];
__device__ bf16  g_qh [ROWS*DM], g_kh[ROWS*DM], g_vh[ROWS*DM];
__device__ bf16  g_ah [ROWS*DM];                       // attention out (Wo input)
__device__ bf16  g_wqh[DM*DM], g_wkh[DM*DM], g_wvh[DM*DM], g_woh[DM*DM], g_w1h[DM*DM];
__device__ float g_t1 [ROWS*DM];
__device__ float g_proj[ROWS*DM];
__device__ float g_tl [ROWS];
__device__ bf16  g_vth[4L*HD*SEQ];                     // V transposed per global head

// ---------------- helpers ----------------
#define MMA_BF16(d, a, b) \
    asm volatile("mma.sync.aligned.m16n8k16.row.col.f32.bf16.bf16.f32 " \
        "{%0,%1,%2,%3},{%4,%5,%6,%7},{%8,%9},{%0,%1,%2,%3};" \
        : "+f"((d)[0]), "+f"((d)[1]), "+f"((d)[2]), "+f"((d)[3]) \
        : "r"((a)[0]), "r"((a)[1]), "r"((a)[2]), "r"((a)[3]), "r"((b)[0]), "r"((b)[1]))

__device__ __forceinline__ float warp_red_sum(float v){
#pragma unroll
    for (int o=16;o;o>>=1) v += __shfl_xor_sync(0xffffffffu, v, o);
    return v;
}
__device__ __forceinline__ float warp_red_max(float v){
#pragma unroll
    for (int o=16;o;o>>=1) v = fmaxf(v, __shfl_xor_sync(0xffffffffu, v, o));
    return v;
}
__device__ float block_red_sum(float v, float* sh){
    __syncthreads();
    int lane = threadIdx.x & 31, wid = threadIdx.x >> 5;
    v = warp_red_sum(v);
    if (lane==0) sh[wid] = v;
    __syncthreads();
    int nw = (blockDim.x + 31) >> 5;
    float r = (threadIdx.x < nw) ? sh[threadIdx.x] : 0.f;
    r = warp_red_sum(r);
    if (threadIdx.x==0) sh[0] = r;
    __syncthreads();
    return sh[0];
}
__device__ float block_red_max(float v, float* sh){
    __syncthreads();
    int lane = threadIdx.x & 31, wid = threadIdx.x >> 5;
    v = warp_red_max(v);
    if (lane==0) sh[wid] = v;
    __syncthreads();
    int nw = (blockDim.x + 31) >> 5;
    float r = (threadIdx.x < nw) ? sh[threadIdx.x] : -1e30f;
    r = warp_red_max(r);
    if (threadIdx.x==0) sh[0] = r;
    __syncthreads();
    return sh[0];
}

// ---------------- input layernorm -> bf16 ----------------
__global__ void ln_bf16(const float* __restrict__ x, const float* __restrict__ g,
                        const float* __restrict__ b, bf16* __restrict__ o){
    __shared__ float sh[33];
    int row = blockIdx.x;
    const float* xr = x + (long)row*DM;
    float s=0.f, s2=0.f;
    for (int d=threadIdx.x; d<DM; d+=blockDim.x){ float v=xr[d]; s+=v; s2+=v*v; }
    s  = block_red_sum(s,  sh);
    s2 = block_red_sum(s2, sh);
    float mu  = s * (1.0f/DM);
    float var = s2 * (1.0f/DM) - mu*mu;
    float inv = rsqrtf(var + EPS);
    for (int d=threadIdx.x; d<DM; d+=blockDim.x)
        o[(long)row*DM + d] = __float2bfloat16((xr[d]-mu)*inv*g[d] + b[d]);
}

// ---------------- weight converts ----------------
__global__ void cvtw(const float* w0,const float* w1,const float* w2,const float* w3,const float* w4,
                     bf16* o0, bf16* o1, bf16* o2, bf16* o3, bf16* o4){
    const float* w; bf16* o;
    switch (blockIdx.y){
        case 0: w=w0; o=o0; break;
        case 1: w=w1; o=o1; break;
        case 2: w=w2; o=o2; break;
        case 3: w=w3; o=o3; break;
        default:w=w4; o=o4; break;
    }
    for (int i = blockIdx.x*blockDim.x + threadIdx.x; i < DM*DM; i += gridDim.x*blockDim.x)
        o[i] = __float2bfloat16(w[i]);
}

// ---------------- fused QKV + tanh-MLP projection GEMM (sync loads) ---------
// z=0..2 -> bf16 out (qh/kh/vh); z=3 -> t1 = tanh(.+bias) fp32
__global__ void __launch_bounds__(256) proj_gemm(
    const bf16* __restrict__ A,
    const bf16* __restrict__ BWq, const bf16* __restrict__ BWk,
    const bf16* __restrict__ BWv, const bf16* __restrict__ BW1,
    bf16* __restrict__ Cq, bf16* __restrict__ Ck, bf16* __restrict__ Cv,
    float* __restrict__ Ct, const float* __restrict__ bias)
{
    constexpr int BM=128, BN=128, WM=4, WN=2;
    constexpr int WTM=BM/WM, WTN=BN/WN, MF=WTM/16, NF=WTN/8, KS=40;
    __shared__ bf16 sA[BM*KS], sB[BN*KS];
    const int tid = threadIdx.x, wid = tid>>5, lane = tid&31;
    const int wm = wid%WM, wn = wid/WM, g = lane>>2, tg = lane&3;
    const int z = blockIdx.z;
    const bf16* B = (z==0)?BWq : (z==1)?BWk : (z==2)?BWv : BW1;
    const int m0 = blockIdx.y*BM, n0 = blockIdx.x*BN;

    float acc[MF][NF][4];
#pragma unroll
    for (int i=0;i<MF;i++)
#pragma unroll
        for (int j=0;j<NF;j++)
#pragma unroll
            for (int t=0;t<4;t++) acc[i][j][t]=0.f;

    for (int k0=0; k0<DM; k0+=32){
#pragma unroll
        for (int i=tid;i<BM*4;i+=256){
            int r=i>>2,c=i&3;
            *(uint4*)&sA[r*KS+c*8] = *(const uint4*)(A+(long)(m0+r)*DM+k0+c*8);
        }
#pragma unroll
        for (int i=tid;i<BN*4;i+=256){
            int r=i>>2,c=i&3;
            *(uint4*)&sB[r*KS+c*8] = *(const uint4*)(B+(long)(n0+r)*DM+k0+c*8);
        }
        __syncthreads();
#pragma unroll
        for (int ks=0; ks<32; ks+=16){
            const int kr = ks + tg*2;
            uint32_t a[MF][4], b[NF][2];
#pragma unroll
            for (int mf=0;mf<MF;mf++){
                int ar = wm*WTM + mf*16 + g;
                a[mf][0]=*(const uint32_t*)&sA[ ar   *KS+kr  ];
                a[mf][1]=*(const uint32_t*)&sA[(ar+8)*KS+kr  ];
                a[mf][2]=*(const uint32_t*)&sA[ ar   *KS+kr+8];
                a[mf][3]=*(const uint32_t*)&sA[(ar+8)*KS+kr+8];
            }
#pragma unroll
            for (int nf=0;nf<NF;nf++){
                int br = wn*WTN + nf*8 + g;
                b[nf][0]=*(const uint32_t*)&sB[br*KS+kr  ];
                b[nf][1]=*(const uint32_t*)&sB[br*KS+kr+8];
            }
#pragma unroll
            for (int mf=0;mf<MF;mf++)
#pragma unroll
                for (int nf=0;nf<NF;nf++)
                    MMA_BF16(acc[mf][nf], a[mf], b[nf]);
        }
        __syncthreads();
    }

    bf16* Cb = (z==0)?Cq : (z==1)?Ck : Cv;
#pragma unroll
    for (int mf=0;mf<MF;mf++){
#pragma unroll
        for (int half=0;half<2;half++){
            long row = m0 + wm*WTM + mf*16 + g + half*8;
#pragma unroll
            for (int nf=0;nf<NF;nf++){
                int col = n0 + wn*WTN + nf*8 + tg*2;
                float v0 = acc[mf][nf][half*2+0];
                float v1 = acc[mf][nf][half*2+1];
                long base = row*(long)DM + col;
                if (z==3){
                    v0 = tanhf(v0 + bias[col]);
                    v1 = tanhf(v1 + bias[col+1]);
                    *(float2*)(Ct + base) = make_float2(v0, v1);
                } else {
                    *(bf162*)(Cb + base) = __floats2bfloat162_rn(v0, v1);
                }
            }
        }
    }
}

// ---------------- Wo GEMM (sync loads, fp32 out) ----------------
__global__ void __launch_bounds__(256) wo_gemm(
    const bf16* __restrict__ A, const bf16* __restrict__ B, float* __restrict__ C)
{
    constexpr int BM=128, BN=128, WM=4, WN=2;
    constexpr int WTM=BM/WM, WTN=BN/WN, MF=WTM/16, NF=WTN/8, KS=40;
    __shared__ bf16 sA[BM*KS], sB[BN*KS];
    const int tid = threadIdx.x, wid = tid>>5, lane = tid&31;
    const int wm = wid%WM, wn = wid/WM, g = lane>>2, tg = lane&3;
    const int m0 = blockIdx.y*BM, n0 = blockIdx.x*BN;

    float acc[MF][NF][4];
#pragma unroll
    for (int i=0;i<MF;i++)
#pragma unroll
        for (int j=0;j<NF;j++)
#pragma unroll
            for (int t=0;t<4;t++) acc[i][j][t]=0.f;

    for (int k0=0; k0<DM; k0+=32){
#pragma unroll
        for (int i=tid;i<BM*4;i+=256){
            int r=i>>2,c=i&3;
            *(uint4*)&sA[r*KS+c*8] = *(const uint4*)(A+(long)(m0+r)*DM+k0+c*8);
        }
#pragma unroll
        for (int i=tid;i<BN*4;i+=256){
            int r=i>>2,c=i&3;
            *(uint4*)&sB[r*KS+c*8] = *(const uint4*)(B+(long)(n0+r)*DM+k0+c*8);
        }
        __syncthreads();
#pragma unroll
        for (int ks=0; ks<32; ks+=16){
            const int kr = ks + tg*2;
            uint32_t a[MF][4], b[NF][2];
#pragma unroll
            for (int mf=0;mf<MF;mf++){
                int ar = wm*WTM + mf*16 + g;
                a[mf][0]=*(const uint32_t*)&sA[ ar   *KS+kr  ];
                a[mf][1]=*(const uint32_t*)&sA[(ar+8)*KS+kr  ];
                a[mf][2]=*(const uint32_t*)&sA[ ar   *KS+kr+8];
                a[mf][3]=*(const uint32_t*)&sA[(ar+8)*KS+kr+8];
            }
#pragma unroll
            for (int nf=0;nf<NF;nf++){
                int br = wn*WTN + nf*8 + g;
                b[nf][0]=*(const uint32_t*)&sB[br*KS+kr  ];
                b[nf][1]=*(const uint32_t*)&sB[br*KS+kr+8];
            }
#pragma unroll
            for (int mf=0;mf<MF;mf++)
#pragma unroll
                for (int nf=0;nf<NF;nf++)
                    MMA_BF16(acc[mf][nf], a[mf], b[nf]);
        }
        __syncthreads();
    }
#pragma unroll
    for (int mf=0;mf<MF;mf++){
#pragma unroll
        for (int half=0;half<2;half++){
            long row = m0 + wm*WTM + mf*16 + g + half*8;
#pragma unroll
            for (int nf=0;nf<NF;nf++){
                int col = n0 + wn*WTN + nf*8 + tg*2;
                *(float2*)(C + row*(long)DM + col) =
                    make_float2(acc[mf][nf][half*2+0], acc[mf][nf][half*2+1]);
            }
        }
    }
}

// ---------------- V transpose (global heads) ----------------
__global__ void vtrans(const bf16* __restrict__ v, bf16* __restrict__ vt){
    __shared__ bf16 t[32][33];
    int z = blockIdx.z, b = z>>1, h = z&1;
    int k0 = blockIdx.x*32, n0 = blockIdx.y*32;
    for (int i = threadIdx.y; i < 32; i += 8)
        t[i][threadIdx.x] = v[(long)(b*SEQ + k0 + i)*DM + h*HD + n0 + threadIdx.x];
    __syncthreads();
    for (int i = threadIdx.y; i < 32; i += 8)
        vt[(long)z*HD*SEQ + (long)(n0+i)*SEQ + k0 + threadIdx.x] = t[threadIdx.x][i];
}

// ---------------- flash attention for global heads (h=0,1) ----------------
// grid (SEQ/64, 4): z -> (batch, head). 128 threads = 4 warps, 16 q-rows/warp.
__global__ void __launch_bounds__(128) flash_attn(
    const bf16* __restrict__ Q, const bf16* __restrict__ K,
    const bf16* __restrict__ Vt, bf16* __restrict__ O)
{
    const int z = blockIdx.y, b = z>>1, h = z&1;
    const int q0 = blockIdx.x*64;
    const int tid = threadIdx.x, w = tid>>5, lane = tid&31;
    const int g = lane>>2, tg = lane&3;

    __shared__ bf16 sQ[64*72];
    __shared__ bf16 sK[128*72];
    __shared__ bf16 sV[HD*136];

    // load Q tile (rows q0..+63, cols h*HD..+63)
    for (int i = tid; i < 64*8; i += 128){
        int r = i>>3, c = i&7;
        *(uint4*)&sQ[r*72 + c*8] = *(const uint4*)(Q + (long)(b*SEQ+q0+r)*DM + h*HD + c*8);
    }

    float m_run[2] = {-1e30f, -1e30f};
    float l_run[2] = {0.f, 0.f};
    float acc_o[8][4];
#pragma unroll
    for (int i=0;i<8;i++)
#pragma unroll
        for (int t=0;t<4;t++) acc_o[i][t]=0.f;

    const int ar = w*16 + g;

    for (int n0 = 0; n0 < SEQ; n0 += 128){
        __syncthreads();
        for (int i = tid; i < 128*8; i += 128){
            int r = i>>3, c = i&7;
            *(uint4*)&sK[r*72 + c*8] = *(const uint4*)(K + (long)(b*SEQ+n0+r)*DM + h*HD + c*8);
        }
        for (int i = tid; i < HD*16; i += 128){
            int r = i>>4, c = i&15;
            *(uint4*)&sV[r*136 + c*8] = *(const uint4*)(Vt + (long)z*HD*SEQ + (long)r*SEQ + n0 + c*8);
        }
        __syncthreads();

        // S = Q K^T  (16 n-frags of 8 keys)
        float s[16][4];
#pragma unroll
        for (int nf=0;nf<16;nf++)
#pragma unroll
            for (int t=0;t<4;t++) s[nf][t]=0.f;
#pragma unroll
        for (int ks=0; ks<4; ks++){
            const int kr = ks*16 + tg*2;
            uint32_t a[4];
            a[0]=*(const uint32_t*)&sQ[ ar   *72+kr  ];
            a[1]=*(const uint32_t*)&sQ[(ar+8)*72+kr  ];
            a[2]=*(const uint32_t*)&sQ[ ar   *72+kr+8];
            a[3]=*(const uint32_t*)&sQ[(ar+8)*72+kr+8];
#pragma unroll
            for (int nf=0;nf<16;nf++){
                int br = nf*8 + g;
                uint32_t bb[2] = { *(const uint32_t*)&sK[br*72+kr],
                                   *(const uint32_t*)&sK[br*72+kr+8] };
                MMA_BF16(s[nf], a, bb);
            }
        }

        // online softmax (rows g, g+8 within warp tile)
        float ml0=-1e30f, ml1=-1e30f;
#pragma unroll
        for (int nf=0;nf<16;nf++){
            ml0 = fmaxf(ml0, fmaxf(s[nf][0], s[nf][1]));
            ml1 = fmaxf(ml1, fmaxf(s[nf][2], s[nf][3]));
        }
#pragma unroll
        for (int off=1; off<4; off<<=1){
            ml0 = fmaxf(ml0, __shfl_xor_sync(0xffffffffu, ml0, off));
            ml1 = fmaxf(ml1, __shfl_xor_sync(0xffffffffu, ml1, off));
        }
        float mn0 = fmaxf(m_run[0], ml0), mn1 = fmaxf(m_run[1], ml1);
        float c0 = __expf((m_run[0]-mn0)*SCALE), c1 = __expf((m_run[1]-mn1)*SCALE);
        m_run[0]=mn0; m_run[1]=mn1;

        float ps0=0.f, ps1=0.f;
        uint32_t apv[8][4];
#pragma unroll
        for (int kf=0;kf<8;kf++){
            float p00 = __expf((s[2*kf  ][0]-mn0)*SCALE);
            float p01 = __expf((s[2*kf  ][1]-mn0)*SCALE);
            float p02 = __expf((s[2*kf  ][2]-mn1)*SCALE);
            float p03 = __expf((s[2*kf  ][3]-mn1)*SCALE);
            float p10 = __expf((s[2*kf+1][0]-mn0)*SCALE);
            float p11 = __expf((s[2*kf+1][1]-mn0)*SCALE);
            float p12 = __expf((s[2*kf+1][2]-mn1)*SCALE);
            float p13 = __expf((s[2*kf+1][3]-mn1)*SCALE);
            ps0 += p00+p01+p10+p11;
            ps1 += p02+p03+p12+p13;
            bf162 t0 = __floats2bfloat162_rn(p00, p01);
            bf162 t1 = __floats2bfloat162_rn(p02, p03);
            bf162 t2 = __floats2bfloat162_rn(p10, p11);
            bf162 t3 = __floats2bfloat162_rn(p12, p13);
            apv[kf][0] = *(uint32_t*)&t0;
            apv[kf][1] = *(uint32_t*)&t1;
            apv[kf][2] = *(uint32_t*)&t2;
            apv[kf][3] = *(uint32_t*)&t3;
        }
        l_run[0] = l_run[0]*c0 + ps0;
        l_run[1] = l_run[1]*c1 + ps1;
#pragma unroll
        for (int dd=0; dd<8; dd++){
            acc_o[dd][0]*=c0; acc_o[dd][1]*=c0;
            acc_o[dd][2]*=c1; acc_o[dd][3]*=c1;
        }
        // O += P V
#pragma unroll
        for (int kf=0;kf<8;kf++){
            const int kr = kf*16 + tg*2;
#pragma unroll
            for (int dd=0; dd<8; dd++){
                int br = dd*8 + g;
                uint32_t bb[2] = { *(const uint32_t*)&sV[br*136+kr],
                                   *(const uint32_t*)&sV[br*136+kr+8] };
                MMA_BF16(acc_o[dd], apv[kf], bb);
            }
        }
    }

    float l0 = l_run[0], l1 = l_run[1];
#pragma unroll
    for (int off=1; off<4; off<<=1){
        l0 += __shfl_xor_sync(0xffffffffu, l0, off);
        l1 += __shfl_xor_sync(0xffffffffu, l1, off);
    }
    float inv0 = 1.0f/l0, inv1 = 1.0f/l1;
    long r0 = (long)(b*SEQ + q0 + ar)*DM + h*HD;
    long r1 = r0 + 8L*DM;
#pragma unroll
    for (int dd=0; dd<8; dd++){
        int col = dd*8 + tg*2;
        *(bf162*)(O + r0 + col) = __floats2bfloat162_rn(acc_o[dd][0]*inv0, acc_o[dd][1]*inv0);
        *(bf162*)(O + r1 + col) = __floats2bfloat162_rn(acc_o[dd][2]*inv1, acc_o[dd][3]*inv1);
    }
}

// ---------------- sparse heads (wide loads) ----------------
__global__ void sparse_attn(const bf16* __restrict__ Q, const bf16* __restrict__ Kk,
                            const bf16* __restrict__ V, bf16* __restrict__ O){
    int hy = blockIdx.y;            // 0..5 -> heads 2..7
    int h  = hy + 2;
    int b  = blockIdx.z;
    int wid = threadIdx.x >> 5, lane = threadIdx.x & 31;
    int q = blockIdx.x*4 + wid;

    int w   = (hy==1) ? 128 : (hy==2) ? 256 : 64;
    int dil = (hy<3)  ? 1   : (1 << (hy-2));

    __shared__ float qs[4][64];
    __shared__ float pbuf[4][520];

    const bf16* qrow = Q + ((long)(b*SEQ + q)*DM + h*HD);
    qs[wid][lane]    = __bfloat162float(qrow[lane]);
    qs[wid][lane+32] = __bfloat162float(qrow[lane+32]);
    __syncwarp();

    int jlo = -min(w, q/dil);
    int jhi =  min(w, (SEQ-1-q)/dil);
    int cnt = jhi - jlo + 1;

    const bf16* Kbase = Kk + ((long)b*SEQ*DM + h*HD);
    const bf16* Vbase = V  + ((long)b*SEQ*DM + h*HD);

    float mmax = -1e30f;
    for (int jj=lane; jj<cnt; jj+=32){
        int k = q + (jlo+jj)*dil;
        const uint4* kr4 = (const uint4*)(Kbase + (long)k*DM);
        float s = 0.f;
#pragma unroll
        for (int u=0; u<8; u++){
            uint4 t = kr4[u];
            float2 f0 = __bfloat1622float2(*(bf162*)&t.x);
            float2 f1 = __bfloat1622float2(*(bf162*)&t.y);
            float2 f2 = __bfloat1622float2(*(bf162*)&t.z);
            float2 f3 = __bfloat1622float2(*(bf162*)&t.w);
            const float* qq = &qs[wid][u*8];
            s += qq[0]*f0.x + qq[1]*f0.y + qq[2]*f1.x + qq[3]*f1.y
               + qq[4]*f2.x + qq[5]*f2.y + qq[6]*f3.x + qq[7]*f3.y;
        }
        s *= SCALE;
        pbuf[wid][jj] = s;
        mmax = fmaxf(mmax, s);
    }
    mmax = warp_red_max(mmax);
    float sum = 0.f;
    for (int jj=lane; jj<cnt; jj+=32){
        float e = __expf(pbuf[wid][jj] - mmax);
        pbuf[wid][jj] = e;
        sum += e;
    }
    sum = warp_red_sum(sum);
    float inv = 1.0f/sum;
    __syncwarp();

    float2 o = make_float2(0.f, 0.f);
#pragma unroll 4
    for (int jj=0; jj<cnt; jj++){
        int k = q + (jlo+jj)*dil;
        float p = pbuf[wid][jj];
        float2 f = __bfloat1622float2(*(const bf162*)(Vbase + (long)k*DM + 2*lane));
        o.x += p*f.x;
        o.y += p*f.y;
    }
    bf16* orow = O + ((long)(b*SEQ + q)*DM + h*HD);
    *(bf162*)(orow + 2*lane) = __floats2bfloat162_rn(o.x*inv, o.y*inv);
}

// ---------------- T gate ----------------
__global__ void tdot_kernel(const float* __restrict__ t1, const float* __restrict__ w2,
                            const float* __restrict__ b2, float* __restrict__ tl){
    __shared__ float sh[33];
    int row = blockIdx.x;
    const float* tr = t1 + (long)row*DM;
    float s = 0.f;
    for (int d=threadIdx.x; d<DM; d+=blockDim.x) s += tr[d]*w2[d];
    s = block_red_sum(s, sh);
    if (threadIdx.x==0) tl[row] = s + b2[0];
}
__global__ void tsoftmax_kernel(float* __restrict__ tl){
    __shared__ float sh[33];
    float* p = tl + (long)blockIdx.x*SEQ;
    int tid = threadIdx.x;
    float v0 = p[tid], v1 = p[tid+1024];
    float m = block_red_max(fmaxf(v0,v1), sh);
    float e0 = __expf(v0-m), e1 = __expf(v1-m);
    float s = block_red_sum(e0+e1, sh);
    float inv = 1.0f/s;
    p[tid] = e0*inv; p[tid+1024] = e1*inv;
}

// ---------------- final: gate, residual, output layernorm ----------------
__global__ void final_kernel(const float* __restrict__ proj, const float* __restrict__ x0,
                             const float* __restrict__ tl, const float* __restrict__ g,
                             const float* __restrict__ b, float* __restrict__ out){
    __shared__ float sh[33];
    int row = blockIdx.x;
    float t = tl[row];
    const float* pr = proj + (long)row*DM;
    const float* xr = x0   + (long)row*DM;
    float s=0.f, s2=0.f;
    for (int d=threadIdx.x; d<DM; d+=blockDim.x){
        float v = pr[d]*t + xr[d];
        s += v; s2 += v*v;
    }
    s  = block_red_sum(s,  sh);
    s2 = block_red_sum(s2, sh);
    float mu  = s * (1.0f/DM);
    float var = s2 * (1.0f/DM) - mu*mu;
    float inv = rsqrtf(var + EPS);
    float* o = out + (long)row*DM;
    for (int d=threadIdx.x; d<DM; d+=blockDim.x){
        float v = pr[d]*t + xr[d];
        o[d] = (v-mu)*inv*g[d] + b[d];
    }
}

// ---------------- launcher ----------------
extern "C" void kernel_launch(void* const* d_in, const int* in_sizes, int n_in,
                              void* d_out, int out_size)
{
    const float* x      = (const float*)d_in[0];
    const float* Wq     = (const float*)d_in[1];
    const float* Wk     = (const float*)d_in[2];
    const float* Wv     = (const float*)d_in[3];
    const float* Wo     = (const float*)d_in[4];
    const float* T_w1   = (const float*)d_in[5];
    const float* T_b1   = (const float*)d_in[6];
    const float* T_w2   = (const float*)d_in[7];
    const float* T_b2   = (const float*)d_in[8];
    const float* ln_in_g  = (const float*)d_in[9];
    const float* ln_in_b  = (const float*)d_in[10];
    const float* ln_out_g = (const float*)d_in[11];
    const float* ln_out_b = (const float*)d_in[12];
    float* out = (float*)d_out;

    bf16 *xnh,*qh,*kh,*vh,*ah,*wqh,*wkh,*wvh,*woh,*w1h,*vth;
    float *t1,*proj,*tl;
    cudaGetSymbolAddress((void**)&xnh, g_xnh);
    cudaGetSymbolAddress((void**)&qh,  g_qh);
    cudaGetSymbolAddress((void**)&kh,  g_kh);
    cudaGetSymbolAddress((void**)&vh,  g_vh);
    cudaGetSymbolAddress((void**)&ah,  g_ah);
    cudaGetSymbolAddress((void**)&wqh, g_wqh);
    cudaGetSymbolAddress((void**)&wkh, g_wkh);
    cudaGetSymbolAddress((void**)&wvh, g_wvh);
    cudaGetSymbolAddress((void**)&woh, g_woh);
    cudaGetSymbolAddress((void**)&w1h, g_w1h);
    cudaGetSymbolAddress((void**)&vth, g_vth);
    cudaGetSymbolAddress((void**)&t1,  g_t1);
    cudaGetSymbolAddress((void**)&proj,g_proj);
    cudaGetSymbolAddress((void**)&tl,  g_tl);

    // 1. input LN -> bf16
    ln_bf16<<<ROWS,128>>>(x, ln_in_g, ln_in_b, xnh);

    // 2. convert weights
    cvtw<<<dim3(64,5),256>>>(Wq,Wk,Wv,Wo,T_w1, wqh,wkh,wvh,woh,w1h);

    // 3. fused projections
    proj_gemm<<<dim3(DM/128, ROWS/128, 4),256>>>(xnh, wqh,wkh,wvh,w1h,
                                                 qh,kh,vh, t1, T_b1);

    // 4. T gate
    tdot_kernel<<<ROWS,128>>>(t1, T_w2, T_b2, tl);
    tsoftmax_kernel<<<BATCH,1024>>>(tl);

    // 5. global heads: V transpose + flash attention -> ah
    vtrans<<<dim3(SEQ/32, HD/32, 4), dim3(32,8)>>>(vh, vth);
    flash_attn<<<dim3(SEQ/64, 4),128>>>(qh, kh, vth, ah);

    // 6. sparse heads (h=2..7) -> ah
    sparse_attn<<<dim3(SEQ/4,6,BATCH),128>>>(qh, kh, vh, ah);

    // 7. output projection
    wo_gemm<<<dim3(DM/128, ROWS/128, 1),256>>>(ah, woh, proj);

    // 8. gate * out + residual + output LN
    final_kernel<<<ROWS,128>>>(proj, x, tl, ln_out_g, ln_out_b, out);
}

// round 6
// speedup vs baseline: 3.2828x; 1.6090x over previous
#include <cuda_runtime.h>
#include <cuda_bf16.h>
#include <math.h>
#include <stdint.h>

#define BATCH 2
#define SEQ   2048
#define DM    512
#define HD    64
#define ROWS  (BATCH*SEQ)
#define SCALE 0.125f
#define EPS   1e-5f

typedef __nv_bfloat16  bf16;
typedef __nv_bfloat162 bf162;

// ---------------- scratch ----------------
__device__ bf16  g_xnh[ROWS*DM];
__device__ bf16  g_qh [ROWS*DM], g_kh[ROWS*DM], g_vh[ROWS*DM];
__device__ bf16  g_ah [ROWS*DM];                       // attention out (Wo input)
__device__ bf16  g_wqh[DM*DM], g_wkh[DM*DM], g_wvh[DM*DM], g_woh[DM*DM], g_w1h[DM*DM];
__device__ float g_t1 [ROWS*DM];
__device__ float g_proj[ROWS*DM];
__device__ float g_tl [ROWS];
__device__ bf16  g_vtp[16L*HD*SEQ];                    // V^T, class-permuted, per (b,h)

// ---------------- helpers ----------------
#define MMA_BF16(d, a, b) \
    asm volatile("mma.sync.aligned.m16n8k16.row.col.f32.bf16.bf16.f32 " \
        "{%0,%1,%2,%3},{%4,%5,%6,%7},{%8,%9},{%0,%1,%2,%3};" \
        : "+f"((d)[0]), "+f"((d)[1]), "+f"((d)[2]), "+f"((d)[3]) \
        : "r"((a)[0]), "r"((a)[1]), "r"((a)[2]), "r"((a)[3]), "r"((b)[0]), "r"((b)[1]))

__device__ __forceinline__ float warp_red_sum(float v){
#pragma unroll
    for (int o=16;o;o>>=1) v += __shfl_xor_sync(0xffffffffu, v, o);
    return v;
}
__device__ __forceinline__ float warp_red_max(float v){
#pragma unroll
    for (int o=16;o;o>>=1) v = fmaxf(v, __shfl_xor_sync(0xffffffffu, v, o));
    return v;
}
__device__ float block_red_sum(float v, float* sh){
    __syncthreads();
    int lane = threadIdx.x & 31, wid = threadIdx.x >> 5;
    v = warp_red_sum(v);
    if (lane==0) sh[wid] = v;
    __syncthreads();
    int nw = (blockDim.x + 31) >> 5;
    float r = (threadIdx.x < nw) ? sh[threadIdx.x] : 0.f;
    r = warp_red_sum(r);
    if (threadIdx.x==0) sh[0] = r;
    __syncthreads();
    return sh[0];
}
__device__ float block_red_max(float v, float* sh){
    __syncthreads();
    int lane = threadIdx.x & 31, wid = threadIdx.x >> 5;
    v = warp_red_max(v);
    if (lane==0) sh[wid] = v;
    __syncthreads();
    int nw = (blockDim.x + 31) >> 5;
    float r = (threadIdx.x < nw) ? sh[threadIdx.x] : -1e30f;
    r = warp_red_max(r);
    if (threadIdx.x==0) sh[0] = r;
    __syncthreads();
    return sh[0];
}

// ---------------- input layernorm -> bf16 ----------------
__global__ void ln_bf16(const float* __restrict__ x, const float* __restrict__ g,
                        const float* __restrict__ b, bf16* __restrict__ o){
    __shared__ float sh[33];
    int row = blockIdx.x;
    const float* xr = x + (long)row*DM;
    float s=0.f, s2=0.f;
    for (int d=threadIdx.x; d<DM; d+=blockDim.x){ float v=xr[d]; s+=v; s2+=v*v; }
    s  = block_red_sum(s,  sh);
    s2 = block_red_sum(s2, sh);
    float mu  = s * (1.0f/DM);
    float var = s2 * (1.0f/DM) - mu*mu;
    float inv = rsqrtf(var + EPS);
    for (int d=threadIdx.x; d<DM; d+=blockDim.x)
        o[(long)row*DM + d] = __float2bfloat16((xr[d]-mu)*inv*g[d] + b[d]);
}

// ---------------- weight converts ----------------
__global__ void cvtw(const float* w0,const float* w1,const float* w2,const float* w3,const float* w4,
                     bf16* o0, bf16* o1, bf16* o2, bf16* o3, bf16* o4){
    const float* w; bf16* o;
    switch (blockIdx.y){
        case 0: w=w0; o=o0; break;
        case 1: w=w1; o=o1; break;
        case 2: w=w2; o=o2; break;
        case 3: w=w3; o=o3; break;
        default:w=w4; o=o4; break;
    }
    for (int i = blockIdx.x*blockDim.x + threadIdx.x; i < DM*DM; i += gridDim.x*blockDim.x)
        o[i] = __float2bfloat16(w[i]);
}

// ---------------- fused QKV + tanh-MLP projection GEMM ----------------
__global__ void __launch_bounds__(256) proj_gemm(
    const bf16* __restrict__ A,
    const bf16* __restrict__ BWq, const bf16* __restrict__ BWk,
    const bf16* __restrict__ BWv, const bf16* __restrict__ BW1,
    bf16* __restrict__ Cq, bf16* __restrict__ Ck, bf16* __restrict__ Cv,
    float* __restrict__ Ct, const float* __restrict__ bias)
{
    constexpr int BM=128, BN=128, WM=4, WN=2;
    constexpr int WTM=BM/WM, WTN=BN/WN, MF=WTM/16, NF=WTN/8, KS=40;
    __shared__ bf16 sA[BM*KS], sB[BN*KS];
    const int tid = threadIdx.x, wid = tid>>5, lane = tid&31;
    const int wm = wid%WM, wn = wid/WM, g = lane>>2, tg = lane&3;
    const int z = blockIdx.z;
    const bf16* B = (z==0)?BWq : (z==1)?BWk : (z==2)?BWv : BW1;
    const int m0 = blockIdx.y*BM, n0 = blockIdx.x*BN;

    float acc[MF][NF][4];
#pragma unroll
    for (int i=0;i<MF;i++)
#pragma unroll
        for (int j=0;j<NF;j++)
#pragma unroll
            for (int t=0;t<4;t++) acc[i][j][t]=0.f;

    for (int k0=0; k0<DM; k0+=32){
#pragma unroll
        for (int i=tid;i<BM*4;i+=256){
            int r=i>>2,c=i&3;
            *(uint4*)&sA[r*KS+c*8] = *(const uint4*)(A+(long)(m0+r)*DM+k0+c*8);
        }
#pragma unroll
        for (int i=tid;i<BN*4;i+=256){
            int r=i>>2,c=i&3;
            *(uint4*)&sB[r*KS+c*8] = *(const uint4*)(B+(long)(n0+r)*DM+k0+c*8);
        }
        __syncthreads();
#pragma unroll
        for (int ks=0; ks<32; ks+=16){
            const int kr = ks + tg*2;
            uint32_t a[MF][4], b[NF][2];
#pragma unroll
            for (int mf=0;mf<MF;mf++){
                int ar = wm*WTM + mf*16 + g;
                a[mf][0]=*(const uint32_t*)&sA[ ar   *KS+kr  ];
                a[mf][1]=*(const uint32_t*)&sA[(ar+8)*KS+kr  ];
                a[mf][2]=*(const uint32_t*)&sA[ ar   *KS+kr+8];
                a[mf][3]=*(const uint32_t*)&sA[(ar+8)*KS+kr+8];
            }
#pragma unroll
            for (int nf=0;nf<NF;nf++){
                int br = wn*WTN + nf*8 + g;
                b[nf][0]=*(const uint32_t*)&sB[br*KS+kr  ];
                b[nf][1]=*(const uint32_t*)&sB[br*KS+kr+8];
            }
#pragma unroll
            for (int mf=0;mf<MF;mf++)
#pragma unroll
                for (int nf=0;nf<NF;nf++)
                    MMA_BF16(acc[mf][nf], a[mf], b[nf]);
        }
        __syncthreads();
    }

    bf16* Cb = (z==0)?Cq : (z==1)?Ck : Cv;
#pragma unroll
    for (int mf=0;mf<MF;mf++){
#pragma unroll
        for (int half=0;half<2;half++){
            long row = m0 + wm*WTM + mf*16 + g + half*8;
#pragma unroll
            for (int nf=0;nf<NF;nf++){
                int col = n0 + wn*WTN + nf*8 + tg*2;
                float v0 = acc[mf][nf][half*2+0];
                float v1 = acc[mf][nf][half*2+1];
                long base = row*(long)DM + col;
                if (z==3){
                    v0 = tanhf(v0 + bias[col]);
                    v1 = tanhf(v1 + bias[col+1]);
                    *(float2*)(Ct + base) = make_float2(v0, v1);
                } else {
                    *(bf162*)(Cb + base) = __floats2bfloat162_rn(v0, v1);
                }
            }
        }
    }
}

// ---------------- Wo GEMM ----------------
__global__ void __launch_bounds__(256) wo_gemm(
    const bf16* __restrict__ A, const bf16* __restrict__ B, float* __restrict__ C)
{
    constexpr int BM=128, BN=128, WM=4, WN=2;
    constexpr int WTM=BM/WM, WTN=BN/WN, MF=WTM/16, NF=WTN/8, KS=40;
    __shared__ bf16 sA[BM*KS], sB[BN*KS];
    const int tid = threadIdx.x, wid = tid>>5, lane = tid&31;
    const int wm = wid%WM, wn = wid/WM, g = lane>>2, tg = lane&3;
    const int m0 = blockIdx.y*BM, n0 = blockIdx.x*BN;

    float acc[MF][NF][4];
#pragma unroll
    for (int i=0;i<MF;i++)
#pragma unroll
        for (int j=0;j<NF;j++)
#pragma unroll
            for (int t=0;t<4;t++) acc[i][j][t]=0.f;

    for (int k0=0; k0<DM; k0+=32){
#pragma unroll
        for (int i=tid;i<BM*4;i+=256){
            int r=i>>2,c=i&3;
            *(uint4*)&sA[r*KS+c*8] = *(const uint4*)(A+(long)(m0+r)*DM+k0+c*8);
        }
#pragma unroll
        for (int i=tid;i<BN*4;i+=256){
            int r=i>>2,c=i&3;
            *(uint4*)&sB[r*KS+c*8] = *(const uint4*)(B+(long)(n0+r)*DM+k0+c*8);
        }
        __syncthreads();
#pragma unroll
        for (int ks=0; ks<32; ks+=16){
            const int kr = ks + tg*2;
            uint32_t a[MF][4], b[NF][2];
#pragma unroll
            for (int mf=0;mf<MF;mf++){
                int ar = wm*WTM + mf*16 + g;
                a[mf][0]=*(const uint32_t*)&sA[ ar   *KS+kr  ];
                a[mf][1]=*(const uint32_t*)&sA[(ar+8)*KS+kr  ];
                a[mf][2]=*(const uint32_t*)&sA[ ar   *KS+kr+8];
                a[mf][3]=*(const uint32_t*)&sA[(ar+8)*KS+kr+8];
            }
#pragma unroll
            for (int nf=0;nf<NF;nf++){
                int br = wn*WTN + nf*8 + g;
                b[nf][0]=*(const uint32_t*)&sB[br*KS+kr  ];
                b[nf][1]=*(const uint32_t*)&sB[br*KS+kr+8];
            }
#pragma unroll
            for (int mf=0;mf<MF;mf++)
#pragma unroll
                for (int nf=0;nf<NF;nf++)
                    MMA_BF16(acc[mf][nf], a[mf], b[nf]);
        }
        __syncthreads();
    }
#pragma unroll
    for (int mf=0;mf<MF;mf++){
#pragma unroll
        for (int half=0;half<2;half++){
            long row = m0 + wm*WTM + mf*16 + g + half*8;
#pragma unroll
            for (int nf=0;nf<NF;nf++){
                int col = n0 + wn*WTN + nf*8 + tg*2;
                *(float2*)(C + row*(long)DM + col) =
                    make_float2(acc[mf][nf][half*2+0], acc[mf][nf][half*2+1]);
            }
        }
    }
}

// ---------------- V transpose, class-permuted, all heads ----------------
// out[z=b*8+h][dd][p] = V[b][k][h*HD+dd],  p = (k%d)*Nc + k/d,  Nc=SEQ/d
__global__ void vtrans_p(const bf16* __restrict__ v, bf16* __restrict__ vt){
    __shared__ bf16 t[32][33];
    int z = blockIdx.z, b = z>>3, h = z&7;
    int d = (h<5) ? 1 : (1 << (h-4));
    int Nc = SEQ/d;
    int k0 = blockIdx.x*32, n0 = blockIdx.y*32;
    for (int i = threadIdx.y; i < 32; i += 8)
        t[i][threadIdx.x] = v[(long)(b*SEQ + k0 + i)*DM + h*HD + n0 + threadIdx.x];
    __syncthreads();
    int k = k0 + threadIdx.x;
    int p = (k % d)*Nc + k/d;
    for (int i = threadIdx.y; i < 32; i += 8)
        vt[(long)z*HD*SEQ + (long)(n0+i)*SEQ + p] = t[threadIdx.x][i];
}

// ---------------- unified banded flash attention (all 8 heads) -------------
// grid (32, 8, 2): x -> class*qblock, y -> head, z -> batch. 128 threads.
__global__ void __launch_bounds__(128) uni_attn(
    const bf16* __restrict__ Q, const bf16* __restrict__ K,
    const bf16* __restrict__ Vt, bf16* __restrict__ O)
{
    const int h = blockIdx.y, b = blockIdx.z;
    const int d = (h<5) ? 1 : (1 << (h-4));
    const int w = (h<2) ? SEQ : (h==2) ? 64 : (h==3) ? 128 : (h==4) ? 256 : 64;
    const int Nc = SEQ/d;
    const int cc = blockIdx.x % d;            // residue class
    const int q0 = (blockIdx.x / d)*64;       // class-coordinate query base
    const bool banded = (w < Nc);

    const int tid = threadIdx.x, wp = tid>>5, lane = tid&31;
    const int g = lane>>2, tg = lane&3;

    __shared__ bf16 sQ[64*72];
    __shared__ bf16 sK[128*72];
    __shared__ bf16 sV[HD*136];

    // Q tile: class rows q0..q0+63 -> global rows cc + (q0+r)*d
    for (int i = tid; i < 64*8; i += 128){
        int r = i>>3, c = i&7;
        *(uint4*)&sQ[r*72 + c*8] =
            *(const uint4*)(Q + (long)(b*SEQ + cc + (q0+r)*d)*DM + h*HD + c*8);
    }

    float m_run[2] = {-1e30f, -1e30f};
    float l_run[2] = {0.f, 0.f};
    float acc_o[8][4];
#pragma unroll
    for (int i=0;i<8;i++)
#pragma unroll
        for (int t=0;t<4;t++) acc_o[i][t]=0.f;

    const int ar = wp*16 + g;
    const long vbase = (long)(b*8 + h)*HD*SEQ + (long)cc*Nc;

    int nlo = q0 - w; if (nlo < 0) nlo = 0; nlo &= ~127;
    int nhi = q0 + 64 + w; if (nhi > Nc) nhi = Nc;

    for (int n0 = nlo; n0 < nhi; n0 += 128){
        __syncthreads();
        for (int i = tid; i < 128*8; i += 128){
            int r = i>>3, c = i&7;
            *(uint4*)&sK[r*72 + c*8] =
                *(const uint4*)(K + (long)(b*SEQ + cc + (n0+r)*d)*DM + h*HD + c*8);
        }
        for (int i = tid; i < HD*16; i += 128){
            int r = i>>4, c = i&15;
            *(uint4*)&sV[r*136 + c*8] =
                *(const uint4*)(Vt + vbase + (long)r*SEQ + n0 + c*8);
        }
        __syncthreads();

        // S = Q K^T
        float s[16][4];
#pragma unroll
        for (int nf=0;nf<16;nf++)
#pragma unroll
            for (int t=0;t<4;t++) s[nf][t]=0.f;
#pragma unroll
        for (int ks=0; ks<4; ks++){
            const int kr = ks*16 + tg*2;
            uint32_t a[4];
            a[0]=*(const uint32_t*)&sQ[ ar   *72+kr  ];
            a[1]=*(const uint32_t*)&sQ[(ar+8)*72+kr  ];
            a[2]=*(const uint32_t*)&sQ[ ar   *72+kr+8];
            a[3]=*(const uint32_t*)&sQ[(ar+8)*72+kr+8];
#pragma unroll
            for (int nf=0;nf<16;nf++){
                int br = nf*8 + g;
                uint32_t bb[2] = { *(const uint32_t*)&sK[br*72+kr],
                                   *(const uint32_t*)&sK[br*72+kr+8] };
                MMA_BF16(s[nf], a, bb);
            }
        }

        // band mask in class coordinates
        if (banded){
            const int qi0 = q0 + ar, qi1 = qi0 + 8;
#pragma unroll
            for (int nf=0;nf<16;nf++){
                int kj = n0 + nf*8 + tg*2;
                if (abs(qi0 -  kj   ) > w) s[nf][0] = -1e30f;
                if (abs(qi0 - (kj+1)) > w) s[nf][1] = -1e30f;
                if (abs(qi1 -  kj   ) > w) s[nf][2] = -1e30f;
                if (abs(qi1 - (kj+1)) > w) s[nf][3] = -1e30f;
            }
        }

        // online softmax
        float ml0=-1e30f, ml1=-1e30f;
#pragma unroll
        for (int nf=0;nf<16;nf++){
            ml0 = fmaxf(ml0, fmaxf(s[nf][0], s[nf][1]));
            ml1 = fmaxf(ml1, fmaxf(s[nf][2], s[nf][3]));
        }
#pragma unroll
        for (int off=1; off<4; off<<=1){
            ml0 = fmaxf(ml0, __shfl_xor_sync(0xffffffffu, ml0, off));
            ml1 = fmaxf(ml1, __shfl_xor_sync(0xffffffffu, ml1, off));
        }
        float mn0 = fmaxf(m_run[0], ml0), mn1 = fmaxf(m_run[1], ml1);
        float c0 = __expf((m_run[0]-mn0)*SCALE), c1 = __expf((m_run[1]-mn1)*SCALE);
        m_run[0]=mn0; m_run[1]=mn1;

        float ps0=0.f, ps1=0.f;
        uint32_t apv[8][4];
#pragma unroll
        for (int kf=0;kf<8;kf++){
            float p00 = __expf((s[2*kf  ][0]-mn0)*SCALE);
            float p01 = __expf((s[2*kf  ][1]-mn0)*SCALE);
            float p02 = __expf((s[2*kf  ][2]-mn1)*SCALE);
            float p03 = __expf((s[2*kf  ][3]-mn1)*SCALE);
            float p10 = __expf((s[2*kf+1][0]-mn0)*SCALE);
            float p11 = __expf((s[2*kf+1][1]-mn0)*SCALE);
            float p12 = __expf((s[2*kf+1][2]-mn1)*SCALE);
            float p13 = __expf((s[2*kf+1][3]-mn1)*SCALE);
            ps0 += p00+p01+p10+p11;
            ps1 += p02+p03+p12+p13;
            bf162 t0 = __floats2bfloat162_rn(p00, p01);
            bf162 t1 = __floats2bfloat162_rn(p02, p03);
            bf162 t2 = __floats2bfloat162_rn(p10, p11);
            bf162 t3 = __floats2bfloat162_rn(p12, p13);
            apv[kf][0] = *(uint32_t*)&t0;
            apv[kf][1] = *(uint32_t*)&t1;
            apv[kf][2] = *(uint32_t*)&t2;
            apv[kf][3] = *(uint32_t*)&t3;
        }
        l_run[0] = l_run[0]*c0 + ps0;
        l_run[1] = l_run[1]*c1 + ps1;
#pragma unroll
        for (int dd=0; dd<8; dd++){
            acc_o[dd][0]*=c0; acc_o[dd][1]*=c0;
            acc_o[dd][2]*=c1; acc_o[dd][3]*=c1;
        }
        // O += P V
#pragma unroll
        for (int kf=0;kf<8;kf++){
            const int kr = kf*16 + tg*2;
#pragma unroll
            for (int dd=0; dd<8; dd++){
                int br = dd*8 + g;
                uint32_t bb[2] = { *(const uint32_t*)&sV[br*136+kr],
                                   *(const uint32_t*)&sV[br*136+kr+8] };
                MMA_BF16(acc_o[dd], apv[kf], bb);
            }
        }
    }

    float l0 = l_run[0], l1 = l_run[1];
#pragma unroll
    for (int off=1; off<4; off<<=1){
        l0 += __shfl_xor_sync(0xffffffffu, l0, off);
        l1 += __shfl_xor_sync(0xffffffffu, l1, off);
    }
    float inv0 = 1.0f/l0, inv1 = 1.0f/l1;
    long r0 = (long)(b*SEQ + cc + (q0 + ar    )*d)*DM + h*HD;
    long r1 = (long)(b*SEQ + cc + (q0 + ar + 8)*d)*DM + h*HD;
#pragma unroll
    for (int dd=0; dd<8; dd++){
        int col = dd*8 + tg*2;
        *(bf162*)(O + r0 + col) = __floats2bfloat162_rn(acc_o[dd][0]*inv0, acc_o[dd][1]*inv0);
        *(bf162*)(O + r1 + col) = __floats2bfloat162_rn(acc_o[dd][2]*inv1, acc_o[dd][3]*inv1);
    }
}

// ---------------- T gate ----------------
__global__ void tdot_kernel(const float* __restrict__ t1, const float* __restrict__ w2,
                            const float* __restrict__ b2, float* __restrict__ tl){
    __shared__ float sh[33];
    int row = blockIdx.x;
    const float* tr = t1 + (long)row*DM;
    float s = 0.f;
    for (int d=threadIdx.x; d<DM; d+=blockDim.x) s += tr[d]*w2[d];
    s = block_red_sum(s, sh);
    if (threadIdx.x==0) tl[row] = s + b2[0];
}
__global__ void tsoftmax_kernel(float* __restrict__ tl){
    __shared__ float sh[33];
    float* p = tl + (long)blockIdx.x*SEQ;
    int tid = threadIdx.x;
    float v0 = p[tid], v1 = p[tid+1024];
    float m = block_red_max(fmaxf(v0,v1), sh);
    float e0 = __expf(v0-m), e1 = __expf(v1-m);
    float s = block_red_sum(e0+e1, sh);
    float inv = 1.0f/s;
    p[tid] = e0*inv; p[tid+1024] = e1*inv;
}

// ---------------- final: gate, residual, output layernorm ----------------
__global__ void final_kernel(const float* __restrict__ proj, const float* __restrict__ x0,
                             const float* __restrict__ tl, const float* __restrict__ g,
                             const float* __restrict__ b, float* __restrict__ out){
    __shared__ float sh[33];
    int row = blockIdx.x;
    float t = tl[row];
    const float* pr = proj + (long)row*DM;
    const float* xr = x0   + (long)row*DM;
    float s=0.f, s2=0.f;
    for (int d=threadIdx.x; d<DM; d+=blockDim.x){
        float v = pr[d]*t + xr[d];
        s += v; s2 += v*v;
    }
    s  = block_red_sum(s,  sh);
    s2 = block_red_sum(s2, sh);
    float mu  = s * (1.0f/DM);
    float var = s2 * (1.0f/DM) - mu*mu;
    float inv = rsqrtf(var + EPS);
    float* o = out + (long)row*DM;
    for (int d=threadIdx.x; d<DM; d+=blockDim.x){
        float v = pr[d]*t + xr[d];
        o[d] = (v-mu)*inv*g[d] + b[d];
    }
}

// ---------------- launcher ----------------
extern "C" void kernel_launch(void* const* d_in, const int* in_sizes, int n_in,
                              void* d_out, int out_size)
{
    const float* x      = (const float*)d_in[0];
    const float* Wq     = (const float*)d_in[1];
    const float* Wk     = (const float*)d_in[2];
    const float* Wv     = (const float*)d_in[3];
    const float* Wo     = (const float*)d_in[4];
    const float* T_w1   = (const float*)d_in[5];
    const float* T_b1   = (const float*)d_in[6];
    const float* T_w2   = (const float*)d_in[7];
    const float* T_b2   = (const float*)d_in[8];
    const float* ln_in_g  = (const float*)d_in[9];
    const float* ln_in_b  = (const float*)d_in[10];
    const float* ln_out_g = (const float*)d_in[11];
    const float* ln_out_b = (const float*)d_in[12];
    float* out = (float*)d_out;

    bf16 *xnh,*qh,*kh,*vh,*ah,*wqh,*wkh,*wvh,*woh,*w1h,*vtp;
    float *t1,*proj,*tl;
    cudaGetSymbolAddress((void**)&xnh, g_xnh);
    cudaGetSymbolAddress((void**)&qh,  g_qh);
    cudaGetSymbolAddress((void**)&kh,  g_kh);
    cudaGetSymbolAddress((void**)&vh,  g_vh);
    cudaGetSymbolAddress((void**)&ah,  g_ah);
    cudaGetSymbolAddress((void**)&wqh, g_wqh);
    cudaGetSymbolAddress((void**)&wkh, g_wkh);
    cudaGetSymbolAddress((void**)&wvh, g_wvh);
    cudaGetSymbolAddress((void**)&woh, g_woh);
    cudaGetSymbolAddress((void**)&w1h, g_w1h);
    cudaGetSymbolAddress((void**)&vtp, g_vtp);
    cudaGetSymbolAddress((void**)&t1,  g_t1);
    cudaGetSymbolAddress((void**)&proj,g_proj);
    cudaGetSymbolAddress((void**)&tl,  g_tl);

    // 1. input LN -> bf16
    ln_bf16<<<ROWS,128>>>(x, ln_in_g, ln_in_b, xnh);

    // 2. convert weights
    cvtw<<<dim3(64,5),256>>>(Wq,Wk,Wv,Wo,T_w1, wqh,wkh,wvh,woh,w1h);

    // 3. fused projections
    proj_gemm<<<dim3(DM/128, ROWS/128, 4),256>>>(xnh, wqh,wkh,wvh,w1h,
                                                 qh,kh,vh, t1, T_b1);

    // 4. T gate
    tdot_kernel<<<ROWS,128>>>(t1, T_w2, T_b2, tl);
    tsoftmax_kernel<<<BATCH,1024>>>(tl);

    // 5. all-head attention: class-permuted V transpose + unified banded flash
    vtrans_p<<<dim3(SEQ/32, HD/32, 16), dim3(32,8)>>>(vh, vtp);
    uni_attn<<<dim3(32, 8, BATCH),128>>>(qh, kh, vtp, ah);

    // 6. output projection
    wo_gemm<<<dim3(DM/128, ROWS/128, 1),256>>>(ah, woh, proj);

    // 7. gate * out + residual + output LN
    final_kernel<<<ROWS,128>>>(proj, x, tl, ln_out_g, ln_out_b, out);
}

// round 7
// speedup vs baseline: 5.3112x; 1.6179x over previous
#include <cuda_runtime.h>
#include <cuda_bf16.h>
#include <math.h>
#include <stdint.h>

#define BATCH 2
#define SEQ   2048
#define DM    512
#define HD    64
#define ROWS  (BATCH*SEQ)
#define SCALE 0.125f
#define EPS   1e-5f

typedef __nv_bfloat16  bf16;
typedef __nv_bfloat162 bf162;

// ---------------- scratch ----------------
__device__ bf16  g_xnh[ROWS*DM];
__device__ bf16  g_qh [ROWS*DM], g_kh[ROWS*DM], g_vh[ROWS*DM];
__device__ bf16  g_ah [ROWS*DM];
__device__ bf16  g_wqh[DM*DM], g_wkh[DM*DM], g_wvh[DM*DM], g_woh[DM*DM], g_w1h[DM*DM];
__device__ float g_proj[ROWS*DM];
__device__ float g_tl [ROWS];
__device__ bf16  g_vtp[16L*HD*SEQ];

// ---------------- helpers ----------------
#define MMA_BF16(d, a, b) \
    asm volatile("mma.sync.aligned.m16n8k16.row.col.f32.bf16.bf16.f32 " \
        "{%0,%1,%2,%3},{%4,%5,%6,%7},{%8,%9},{%0,%1,%2,%3};" \
        : "+f"((d)[0]), "+f"((d)[1]), "+f"((d)[2]), "+f"((d)[3]) \
        : "r"((a)[0]), "r"((a)[1]), "r"((a)[2]), "r"((a)[3]), "r"((b)[0]), "r"((b)[1]))

__device__ __forceinline__ float warp_red_sum(float v){
#pragma unroll
    for (int o=16;o;o>>=1) v += __shfl_xor_sync(0xffffffffu, v, o);
    return v;
}
__device__ __forceinline__ float warp_red_max(float v){
#pragma unroll
    for (int o=16;o;o>>=1) v = fmaxf(v, __shfl_xor_sync(0xffffffffu, v, o));
    return v;
}
__device__ float block_red_sum(float v, float* sh){
    __syncthreads();
    int lane = threadIdx.x & 31, wid = threadIdx.x >> 5;
    v = warp_red_sum(v);
    if (lane==0) sh[wid] = v;
    __syncthreads();
    int nw = (blockDim.x + 31) >> 5;
    float r = (threadIdx.x < nw) ? sh[threadIdx.x] : 0.f;
    r = warp_red_sum(r);
    if (threadIdx.x==0) sh[0] = r;
    __syncthreads();
    return sh[0];
}
__device__ float block_red_max(float v, float* sh){
    __syncthreads();
    int lane = threadIdx.x & 31, wid = threadIdx.x >> 5;
    v = warp_red_max(v);
    if (lane==0) sh[wid] = v;
    __syncthreads();
    int nw = (blockDim.x + 31) >> 5;
    float r = (threadIdx.x < nw) ? sh[threadIdx.x] : -1e30f;
    r = warp_red_max(r);
    if (threadIdx.x==0) sh[0] = r;
    __syncthreads();
    return sh[0];
}

// ---------------- input layernorm -> bf16 ----------------
__global__ void ln_bf16(const float* __restrict__ x, const float* __restrict__ g,
                        const float* __restrict__ b, bf16* __restrict__ o){
    __shared__ float sh[33];
    int row = blockIdx.x;
    const float* xr = x + (long)row*DM;
    float s=0.f, s2=0.f;
    for (int d=threadIdx.x; d<DM; d+=blockDim.x){ float v=xr[d]; s+=v; s2+=v*v; }
    s  = block_red_sum(s,  sh);
    s2 = block_red_sum(s2, sh);
    float mu  = s * (1.0f/DM);
    float var = s2 * (1.0f/DM) - mu*mu;
    float inv = rsqrtf(var + EPS);
    for (int d=threadIdx.x; d<DM; d+=blockDim.x)
        o[(long)row*DM + d] = __float2bfloat16((xr[d]-mu)*inv*g[d] + b[d]);
}

// ---------------- weight converts ----------------
__global__ void cvtw(const float* w0,const float* w1,const float* w2,const float* w3,const float* w4,
                     bf16* o0, bf16* o1, bf16* o2, bf16* o3, bf16* o4){
    const float* w; bf16* o;
    switch (blockIdx.y){
        case 0: w=w0; o=o0; break;
        case 1: w=w1; o=o1; break;
        case 2: w=w2; o=o2; break;
        case 3: w=w3; o=o3; break;
        default:w=w4; o=o4; break;
    }
    for (int i = blockIdx.x*blockDim.x + threadIdx.x; i < DM*DM; i += gridDim.x*blockDim.x)
        o[i] = __float2bfloat16(w[i]);
}

// ---------------- fused QKV + tanh-MLP projections, double-buffered ---------
// z=0..2 -> bf16 (qh/kh/vh); z=3 -> T-gate: atomicAdd(tl[row], tanh(v+b1).w2)
__global__ void __launch_bounds__(256) proj_gemm(
    const bf16* __restrict__ A,
    const bf16* __restrict__ BWq, const bf16* __restrict__ BWk,
    const bf16* __restrict__ BWv, const bf16* __restrict__ BW1,
    bf16* __restrict__ Cq, bf16* __restrict__ Ck, bf16* __restrict__ Cv,
    float* __restrict__ tl, const float* __restrict__ bias,
    const float* __restrict__ w2)
{
    constexpr int BM=128, BN=128, WM=4, WN=2;
    constexpr int WTM=BM/WM, WTN=BN/WN, MF=WTM/16, NF=WTN/8, KS=40;
    __shared__ bf16 sA[2][BM*KS], sB[2][BN*KS];
    const int tid = threadIdx.x, wid = tid>>5, lane = tid&31;
    const int wm = wid%WM, wn = wid/WM, g = lane>>2, tg = lane&3;
    const int z = blockIdx.z;
    const bf16* B = (z==0)?BWq : (z==1)?BWk : (z==2)?BWv : BW1;
    const int m0 = blockIdx.y*BM, n0 = blockIdx.x*BN;

    // per-thread fixed load slots: 2 for A, 2 for B
    const int a_r0 = tid>>2,       a_c0 = tid&3;
    const int a_r1 = (tid+256)>>2, a_c1 = (tid+256)&3;
    const int b_r0 = a_r0, b_c0 = a_c0, b_r1 = a_r1, b_c1 = a_c1;

    float acc[MF][NF][4];
#pragma unroll
    for (int i=0;i<MF;i++)
#pragma unroll
        for (int j=0;j<NF;j++)
#pragma unroll
            for (int t=0;t<4;t++) acc[i][j][t]=0.f;

    const int NC = DM>>5;
    // prologue: chunk 0 -> buffer 0
    *(uint4*)&sA[0][a_r0*KS+a_c0*8] = *(const uint4*)(A+(long)(m0+a_r0)*DM+a_c0*8);
    *(uint4*)&sA[0][a_r1*KS+a_c1*8] = *(const uint4*)(A+(long)(m0+a_r1)*DM+a_c1*8);
    *(uint4*)&sB[0][b_r0*KS+b_c0*8] = *(const uint4*)(B+(long)(n0+b_r0)*DM+b_c0*8);
    *(uint4*)&sB[0][b_r1*KS+b_c1*8] = *(const uint4*)(B+(long)(n0+b_r1)*DM+b_c1*8);
    __syncthreads();

    for (int c=0;c<NC;c++){
        uint4 ra0, ra1, rb0, rb1;
        const bool pf = (c+1 < NC);
        if (pf){
            const int k0n = (c+1)<<5;
            ra0 = *(const uint4*)(A+(long)(m0+a_r0)*DM+k0n+a_c0*8);
            ra1 = *(const uint4*)(A+(long)(m0+a_r1)*DM+k0n+a_c1*8);
            rb0 = *(const uint4*)(B+(long)(n0+b_r0)*DM+k0n+b_c0*8);
            rb1 = *(const uint4*)(B+(long)(n0+b_r1)*DM+k0n+b_c1*8);
        }
        const bf16* pA = sA[c&1]; const bf16* pB = sB[c&1];
#pragma unroll
        for (int ks=0; ks<32; ks+=16){
            const int kr = ks + tg*2;
            uint32_t a[MF][4], b[NF][2];
#pragma unroll
            for (int mf=0;mf<MF;mf++){
                int ar = wm*WTM + mf*16 + g;
                a[mf][0]=*(const uint32_t*)&pA[ ar   *KS+kr  ];
                a[mf][1]=*(const uint32_t*)&pA[(ar+8)*KS+kr  ];
                a[mf][2]=*(const uint32_t*)&pA[ ar   *KS+kr+8];
                a[mf][3]=*(const uint32_t*)&pA[(ar+8)*KS+kr+8];
            }
#pragma unroll
            for (int nf=0;nf<NF;nf++){
                int br = wn*WTN + nf*8 + g;
                b[nf][0]=*(const uint32_t*)&pB[br*KS+kr  ];
                b[nf][1]=*(const uint32_t*)&pB[br*KS+kr+8];
            }
#pragma unroll
            for (int mf=0;mf<MF;mf++)
#pragma unroll
                for (int nf=0;nf<NF;nf++)
                    MMA_BF16(acc[mf][nf], a[mf], b[nf]);
        }
        __syncthreads();
        if (pf){
            bf16* nA = sA[(c+1)&1]; bf16* nB = sB[(c+1)&1];
            *(uint4*)&nA[a_r0*KS+a_c0*8] = ra0;
            *(uint4*)&nA[a_r1*KS+a_c1*8] = ra1;
            *(uint4*)&nB[b_r0*KS+b_c0*8] = rb0;
            *(uint4*)&nB[b_r1*KS+b_c1*8] = rb1;
            __syncthreads();
        }
    }

    if (z==3){
#pragma unroll
        for (int mf=0;mf<MF;mf++){
#pragma unroll
            for (int half=0;half<2;half++){
                int row = m0 + wm*WTM + mf*16 + g + half*8;
                float part = 0.f;
#pragma unroll
                for (int nf=0;nf<NF;nf++){
                    int col = n0 + wn*WTN + nf*8 + tg*2;
                    float v0 = tanhf(acc[mf][nf][half*2+0] + bias[col]);
                    float v1 = tanhf(acc[mf][nf][half*2+1] + bias[col+1]);
                    part += v0*w2[col] + v1*w2[col+1];
                }
                atomicAdd(&tl[row], part);
            }
        }
    } else {
        bf16* Cb = (z==0)?Cq : (z==1)?Ck : Cv;
#pragma unroll
        for (int mf=0;mf<MF;mf++){
#pragma unroll
            for (int half=0;half<2;half++){
                long row = m0 + wm*WTM + mf*16 + g + half*8;
#pragma unroll
                for (int nf=0;nf<NF;nf++){
                    int col = n0 + wn*WTN + nf*8 + tg*2;
                    *(bf162*)(Cb + row*(long)DM + col) =
                        __floats2bfloat162_rn(acc[mf][nf][half*2+0], acc[mf][nf][half*2+1]);
                }
            }
        }
    }
}

// ---------------- Wo GEMM, double-buffered, fp32 out ----------------
__global__ void __launch_bounds__(256) wo_gemm(
    const bf16* __restrict__ A, const bf16* __restrict__ B, float* __restrict__ C)
{
    constexpr int BM=128, BN=128, WM=4, WN=2;
    constexpr int WTM=BM/WM, WTN=BN/WN, MF=WTM/16, NF=WTN/8, KS=40;
    __shared__ bf16 sA[2][BM*KS], sB[2][BN*KS];
    const int tid = threadIdx.x, wid = tid>>5, lane = tid&31;
    const int wm = wid%WM, wn = wid/WM, g = lane>>2, tg = lane&3;
    const int m0 = blockIdx.y*BM, n0 = blockIdx.x*BN;

    const int a_r0 = tid>>2,       a_c0 = tid&3;
    const int a_r1 = (tid+256)>>2, a_c1 = (tid+256)&3;

    float acc[MF][NF][4];
#pragma unroll
    for (int i=0;i<MF;i++)
#pragma unroll
        for (int j=0;j<NF;j++)
#pragma unroll
            for (int t=0;t<4;t++) acc[i][j][t]=0.f;

    const int NC = DM>>5;
    *(uint4*)&sA[0][a_r0*KS+a_c0*8] = *(const uint4*)(A+(long)(m0+a_r0)*DM+a_c0*8);
    *(uint4*)&sA[0][a_r1*KS+a_c1*8] = *(const uint4*)(A+(long)(m0+a_r1)*DM+a_c1*8);
    *(uint4*)&sB[0][a_r0*KS+a_c0*8] = *(const uint4*)(B+(long)(n0+a_r0)*DM+a_c0*8);
    *(uint4*)&sB[0][a_r1*KS+a_c1*8] = *(const uint4*)(B+(long)(n0+a_r1)*DM+a_c1*8);
    __syncthreads();

    for (int c=0;c<NC;c++){
        uint4 ra0, ra1, rb0, rb1;
        const bool pf = (c+1 < NC);
        if (pf){
            const int k0n = (c+1)<<5;
            ra0 = *(const uint4*)(A+(long)(m0+a_r0)*DM+k0n+a_c0*8);
            ra1 = *(const uint4*)(A+(long)(m0+a_r1)*DM+k0n+a_c1*8);
            rb0 = *(const uint4*)(B+(long)(n0+a_r0)*DM+k0n+a_c0*8);
            rb1 = *(const uint4*)(B+(long)(n0+a_r1)*DM+k0n+a_c1*8);
        }
        const bf16* pA = sA[c&1]; const bf16* pB = sB[c&1];
#pragma unroll
        for (int ks=0; ks<32; ks+=16){
            const int kr = ks + tg*2;
            uint32_t a[MF][4], b[NF][2];
#pragma unroll
            for (int mf=0;mf<MF;mf++){
                int ar = wm*WTM + mf*16 + g;
                a[mf][0]=*(const uint32_t*)&pA[ ar   *KS+kr  ];
                a[mf][1]=*(const uint32_t*)&pA[(ar+8)*KS+kr  ];
                a[mf][2]=*(const uint32_t*)&pA[ ar   *KS+kr+8];
                a[mf][3]=*(const uint32_t*)&pA[(ar+8)*KS+kr+8];
            }
#pragma unroll
            for (int nf=0;nf<NF;nf++){
                int br = wn*WTN + nf*8 + g;
                b[nf][0]=*(const uint32_t*)&pB[br*KS+kr  ];
                b[nf][1]=*(const uint32_t*)&pB[br*KS+kr+8];
            }
#pragma unroll
            for (int mf=0;mf<MF;mf++)
#pragma unroll
                for (int nf=0;nf<NF;nf++)
                    MMA_BF16(acc[mf][nf], a[mf], b[nf]);
        }
        __syncthreads();
        if (pf){
            bf16* nA = sA[(c+1)&1]; bf16* nB = sB[(c+1)&1];
            *(uint4*)&nA[a_r0*KS+a_c0*8] = ra0;
            *(uint4*)&nA[a_r1*KS+a_c1*8] = ra1;
            *(uint4*)&nB[a_r0*KS+a_c0*8] = rb0;
            *(uint4*)&nB[a_r1*KS+a_c1*8] = rb1;
            __syncthreads();
        }
    }
#pragma unroll
    for (int mf=0;mf<MF;mf++){
#pragma unroll
        for (int half=0;half<2;half++){
            long row = m0 + wm*WTM + mf*16 + g + half*8;
#pragma unroll
            for (int nf=0;nf<NF;nf++){
                int col = n0 + wn*WTN + nf*8 + tg*2;
                *(float2*)(C + row*(long)DM + col) =
                    make_float2(acc[mf][nf][half*2+0], acc[mf][nf][half*2+1]);
            }
        }
    }
}

// ---------------- V transpose, class-permuted ----------------
__global__ void vtrans_p(const bf16* __restrict__ v, bf16* __restrict__ vt){
    __shared__ bf16 t[32][33];
    int z = blockIdx.z, b = z>>3, h = z&7;
    int d = (h<5) ? 1 : (1 << (h-4));
    int Nc = SEQ/d;
    int k0 = blockIdx.x*32, n0 = blockIdx.y*32;
    for (int i = threadIdx.y; i < 32; i += 8)
        t[i][threadIdx.x] = v[(long)(b*SEQ + k0 + i)*DM + h*HD + n0 + threadIdx.x];
    __syncthreads();
    int k = k0 + threadIdx.x;
    int p = (k % d)*Nc + k/d;
    for (int i = threadIdx.y; i < 32; i += 8)
        vt[(long)z*HD*SEQ + (long)(n0+i)*SEQ + p] = t[threadIdx.x][i];
}

// ---------------- unified banded flash attention (all 8 heads) -------------
__global__ void __launch_bounds__(128) uni_attn(
    const bf16* __restrict__ Q, const bf16* __restrict__ K,
    const bf16* __restrict__ Vt, bf16* __restrict__ O)
{
    const int h = blockIdx.y, b = blockIdx.z;
    const int d = (h<5) ? 1 : (1 << (h-4));
    const int w = (h<2) ? SEQ : (h==2) ? 64 : (h==3) ? 128 : (h==4) ? 256 : 64;
    const int Nc = SEQ/d;
    const int cc = blockIdx.x % d;
    const int q0 = (blockIdx.x / d)*64;
    const bool banded = (w < Nc);

    const int tid = threadIdx.x, wp = tid>>5, lane = tid&31;
    const int g = lane>>2, tg = lane&3;

    __shared__ bf16 sQ[64*72];
    __shared__ bf16 sK[128*72];
    __shared__ bf16 sV[HD*136];

    for (int i = tid; i < 64*8; i += 128){
        int r = i>>3, c = i&7;
        *(uint4*)&sQ[r*72 + c*8] =
            *(const uint4*)(Q + (long)(b*SEQ + cc + (q0+r)*d)*DM + h*HD + c*8);
    }

    float m_run[2] = {-1e30f, -1e30f};
    float l_run[2] = {0.f, 0.f};
    float acc_o[8][4];
#pragma unroll
    for (int i=0;i<8;i++)
#pragma unroll
        for (int t=0;t<4;t++) acc_o[i][t]=0.f;

    const int ar = wp*16 + g;
    const long vbase = (long)(b*8 + h)*HD*SEQ + (long)cc*Nc;

    int nlo = q0 - w; if (nlo < 0) nlo = 0; nlo &= ~127;
    int nhi = q0 + 64 + w; if (nhi > Nc) nhi = Nc;

    for (int n0 = nlo; n0 < nhi; n0 += 128){
        __syncthreads();
        for (int i = tid; i < 128*8; i += 128){
            int r = i>>3, c = i&7;
            *(uint4*)&sK[r*72 + c*8] =
                *(const uint4*)(K + (long)(b*SEQ + cc + (n0+r)*d)*DM + h*HD + c*8);
        }
        for (int i = tid; i < HD*16; i += 128){
            int r = i>>4, c = i&15;
            *(uint4*)&sV[r*136 + c*8] =
                *(const uint4*)(Vt + vbase + (long)r*SEQ + n0 + c*8);
        }
        __syncthreads();

        float s[16][4];
#pragma unroll
        for (int nf=0;nf<16;nf++)
#pragma unroll
            for (int t=0;t<4;t++) s[nf][t]=0.f;
#pragma unroll
        for (int ks=0; ks<4; ks++){
            const int kr = ks*16 + tg*2;
            uint32_t a[4];
            a[0]=*(const uint32_t*)&sQ[ ar   *72+kr  ];
            a[1]=*(const uint32_t*)&sQ[(ar+8)*72+kr  ];
            a[2]=*(const uint32_t*)&sQ[ ar   *72+kr+8];
            a[3]=*(const uint32_t*)&sQ[(ar+8)*72+kr+8];
#pragma unroll
            for (int nf=0;nf<16;nf++){
                int br = nf*8 + g;
                uint32_t bb[2] = { *(const uint32_t*)&sK[br*72+kr],
                                   *(const uint32_t*)&sK[br*72+kr+8] };
                MMA_BF16(s[nf], a, bb);
            }
        }

        if (banded){
            const int qi0 = q0 + ar, qi1 = qi0 + 8;
#pragma unroll
            for (int nf=0;nf<16;nf++){
                int kj = n0 + nf*8 + tg*2;
                if (abs(qi0 -  kj   ) > w) s[nf][0] = -1e30f;
                if (abs(qi0 - (kj+1)) > w) s[nf][1] = -1e30f;
                if (abs(qi1 -  kj   ) > w) s[nf][2] = -1e30f;
                if (abs(qi1 - (kj+1)) > w) s[nf][3] = -1e30f;
            }
        }

        float ml0=-1e30f, ml1=-1e30f;
#pragma unroll
        for (int nf=0;nf<16;nf++){
            ml0 = fmaxf(ml0, fmaxf(s[nf][0], s[nf][1]));
            ml1 = fmaxf(ml1, fmaxf(s[nf][2], s[nf][3]));
        }
#pragma unroll
        for (int off=1; off<4; off<<=1){
            ml0 = fmaxf(ml0, __shfl_xor_sync(0xffffffffu, ml0, off));
            ml1 = fmaxf(ml1, __shfl_xor_sync(0xffffffffu, ml1, off));
        }
        float mn0 = fmaxf(m_run[0], ml0), mn1 = fmaxf(m_run[1], ml1);
        float c0 = __expf((m_run[0]-mn0)*SCALE), c1 = __expf((m_run[1]-mn1)*SCALE);
        m_run[0]=mn0; m_run[1]=mn1;

        float ps0=0.f, ps1=0.f;
        uint32_t apv[8][4];
#pragma unroll
        for (int kf=0;kf<8;kf++){
            float p00 = __expf((s[2*kf  ][0]-mn0)*SCALE);
            float p01 = __expf((s[2*kf  ][1]-mn0)*SCALE);
            float p02 = __expf((s[2*kf  ][2]-mn1)*SCALE);
            float p03 = __expf((s[2*kf  ][3]-mn1)*SCALE);
            float p10 = __expf((s[2*kf+1][0]-mn0)*SCALE);
            float p11 = __expf((s[2*kf+1][1]-mn0)*SCALE);
            float p12 = __expf((s[2*kf+1][2]-mn1)*SCALE);
            float p13 = __expf((s[2*kf+1][3]-mn1)*SCALE);
            ps0 += p00+p01+p10+p11;
            ps1 += p02+p03+p12+p13;
            bf162 t0 = __floats2bfloat162_rn(p00, p01);
            bf162 t1 = __floats2bfloat162_rn(p02, p03);
            bf162 t2 = __floats2bfloat162_rn(p10, p11);
            bf162 t3 = __floats2bfloat162_rn(p12, p13);
            apv[kf][0] = *(uint32_t*)&t0;
            apv[kf][1] = *(uint32_t*)&t1;
            apv[kf][2] = *(uint32_t*)&t2;
            apv[kf][3] = *(uint32_t*)&t3;
        }
        l_run[0] = l_run[0]*c0 + ps0;
        l_run[1] = l_run[1]*c1 + ps1;
#pragma unroll
        for (int dd=0; dd<8; dd++){
            acc_o[dd][0]*=c0; acc_o[dd][1]*=c0;
            acc_o[dd][2]*=c1; acc_o[dd][3]*=c1;
        }
#pragma unroll
        for (int kf=0;kf<8;kf++){
            const int kr = kf*16 + tg*2;
#pragma unroll
            for (int dd=0; dd<8; dd++){
                int br = dd*8 + g;
                uint32_t bb[2] = { *(const uint32_t*)&sV[br*136+kr],
                                   *(const uint32_t*)&sV[br*136+kr+8] };
                MMA_BF16(acc_o[dd], apv[kf], bb);
            }
        }
    }

    float l0 = l_run[0], l1 = l_run[1];
#pragma unroll
    for (int off=1; off<4; off<<=1){
        l0 += __shfl_xor_sync(0xffffffffu, l0, off);
        l1 += __shfl_xor_sync(0xffffffffu, l1, off);
    }
    float inv0 = 1.0f/l0, inv1 = 1.0f/l1;
    long r0 = (long)(b*SEQ + cc + (q0 + ar    )*d)*DM + h*HD;
    long r1 = (long)(b*SEQ + cc + (q0 + ar + 8)*d)*DM + h*HD;
#pragma unroll
    for (int dd=0; dd<8; dd++){
        int col = dd*8 + tg*2;
        *(bf162*)(O + r0 + col) = __floats2bfloat162_rn(acc_o[dd][0]*inv0, acc_o[dd][1]*inv0);
        *(bf162*)(O + r1 + col) = __floats2bfloat162_rn(acc_o[dd][2]*inv1, acc_o[dd][3]*inv1);
    }
}

// ---------------- T softmax over sequence ----------------
__global__ void tsoftmax_kernel(float* __restrict__ tl){
    __shared__ float sh[33];
    float* p = tl + (long)blockIdx.x*SEQ;
    int tid = threadIdx.x;
    float v0 = p[tid], v1 = p[tid+1024];
    float m = block_red_max(fmaxf(v0,v1), sh);
    float e0 = __expf(v0-m), e1 = __expf(v1-m);
    float s = block_red_sum(e0+e1, sh);
    float inv = 1.0f/s;
    p[tid] = e0*inv; p[tid+1024] = e1*inv;
}

// ---------------- final: gate, residual, output layernorm ----------------
__global__ void final_kernel(const float* __restrict__ proj, const float* __restrict__ x0,
                             const float* __restrict__ tl, const float* __restrict__ g,
                             const float* __restrict__ b, float* __restrict__ out){
    __shared__ float sh[33];
    int row = blockIdx.x;
    float t = tl[row];
    const float* pr = proj + (long)row*DM;
    const float* xr = x0   + (long)row*DM;
    float s=0.f, s2=0.f;
    for (int d=threadIdx.x; d<DM; d+=blockDim.x){
        float v = pr[d]*t + xr[d];
        s += v; s2 += v*v;
    }
    s  = block_red_sum(s,  sh);
    s2 = block_red_sum(s2, sh);
    float mu  = s * (1.0f/DM);
    float var = s2 * (1.0f/DM) - mu*mu;
    float inv = rsqrtf(var + EPS);
    float* o = out + (long)row*DM;
    for (int d=threadIdx.x; d<DM; d+=blockDim.x){
        float v = pr[d]*t + xr[d];
        o[d] = (v-mu)*inv*g[d] + b[d];
    }
}

// ---------------- launcher ----------------
extern "C" void kernel_launch(void* const* d_in, const int* in_sizes, int n_in,
                              void* d_out, int out_size)
{
    const float* x      = (const float*)d_in[0];
    const float* Wq     = (const float*)d_in[1];
    const float* Wk     = (const float*)d_in[2];
    const float* Wv     = (const float*)d_in[3];
    const float* Wo     = (const float*)d_in[4];
    const float* T_w1   = (const float*)d_in[5];
    const float* T_b1   = (const float*)d_in[6];
    const float* T_w2   = (const float*)d_in[7];
    const float* ln_in_g  = (const float*)d_in[9];
    const float* ln_in_b  = (const float*)d_in[10];
    const float* ln_out_g = (const float*)d_in[11];
    const float* ln_out_b = (const float*)d_in[12];
    float* out = (float*)d_out;

    bf16 *xnh,*qh,*kh,*vh,*ah,*wqh,*wkh,*wvh,*woh,*w1h,*vtp;
    float *proj,*tl;
    cudaGetSymbolAddress((void**)&xnh, g_xnh);
    cudaGetSymbolAddress((void**)&qh,  g_qh);
    cudaGetSymbolAddress((void**)&kh,  g_kh);
    cudaGetSymbolAddress((void**)&vh,  g_vh);
    cudaGetSymbolAddress((void**)&ah,  g_ah);
    cudaGetSymbolAddress((void**)&wqh, g_wqh);
    cudaGetSymbolAddress((void**)&wkh, g_wkh);
    cudaGetSymbolAddress((void**)&wvh, g_wvh);
    cudaGetSymbolAddress((void**)&woh, g_woh);
    cudaGetSymbolAddress((void**)&w1h, g_w1h);
    cudaGetSymbolAddress((void**)&vtp, g_vtp);
    cudaGetSymbolAddress((void**)&proj,g_proj);
    cudaGetSymbolAddress((void**)&tl,  g_tl);

    // 0. zero T-gate accumulators (graph-capturable)
    cudaMemsetAsync(tl, 0, ROWS*sizeof(float));

    // 1. input LN -> bf16
    ln_bf16<<<ROWS,128>>>(x, ln_in_g, ln_in_b, xnh);

    // 2. convert weights
    cvtw<<<dim3(64,5),256>>>(Wq,Wk,Wv,Wo,T_w1, wqh,wkh,wvh,woh,w1h);

    // 3. fused projections + T-gate dot (z=3)
    proj_gemm<<<dim3(DM/128, ROWS/128, 4),256>>>(xnh, wqh,wkh,wvh,w1h,
                                                 qh,kh,vh, tl, T_b1, T_w1 ? (const float*)d_in[7] : nullptr);

    // 4. T softmax over sequence (b2 is a constant shift -> cancels)
    tsoftmax_kernel<<<BATCH,1024>>>(tl);

    // 5. all-head attention
    vtrans_p<<<dim3(SEQ/32, HD/32, 16), dim3(32,8)>>>(vh, vtp);
    uni_attn<<<dim3(32, 8, BATCH),128>>>(qh, kh, vtp, ah);

    // 6. output projection
    wo_gemm<<<dim3(DM/128, ROWS/128, 1),256>>>(ah, woh, proj);

    // 7. gate * out + residual + output LN
    final_kernel<<<ROWS,128>>>(proj, x, tl, ln_out_g, ln_out_b, out);
}

// round 8
// speedup vs baseline: 5.7665x; 1.0857x over previous
#include <cuda_runtime.h>
#include <cuda_bf16.h>
#include <math.h>
#include <stdint.h>

#define BATCH 2
#define SEQ   2048
#define DM    512
#define HD    64
#define ROWS  (BATCH*SEQ)
#define SCALE 0.125f
#define EPS   1e-5f

typedef __nv_bfloat16  bf16;
typedef __nv_bfloat162 bf162;

// ---------------- scratch ----------------
__device__ bf16  g_xnh[ROWS*DM];
__device__ bf16  g_qh [ROWS*DM], g_kh[ROWS*DM], g_vh[ROWS*DM];
__device__ bf16  g_ah [ROWS*DM];
__device__ bf16  g_wqh[DM*DM], g_wkh[DM*DM], g_wvh[DM*DM], g_woh[DM*DM], g_w1h[DM*DM];
__device__ bf16  g_projb[ROWS*DM];
__device__ float g_tl [ROWS];
__device__ bf16  g_vtp[16L*HD*SEQ];

// ---------------- helpers ----------------
__device__ __forceinline__ void cpa16(void* dst, const void* src){
    uint32_t d = (uint32_t)__cvta_generic_to_shared(dst);
    asm volatile("cp.async.cg.shared.global [%0], [%1], 16;\n" :: "r"(d), "l"(src));
}
#define CP_COMMIT() asm volatile("cp.async.commit_group;\n" ::: "memory")
#define CP_WAIT0()  asm volatile("cp.async.wait_group 0;\n" ::: "memory")
#define CP_WAIT1()  asm volatile("cp.async.wait_group 1;\n" ::: "memory")

#define MMA_BF16(d, a, b) \
    asm volatile("mma.sync.aligned.m16n8k16.row.col.f32.bf16.bf16.f32 " \
        "{%0,%1,%2,%3},{%4,%5,%6,%7},{%8,%9},{%0,%1,%2,%3};" \
        : "+f"((d)[0]), "+f"((d)[1]), "+f"((d)[2]), "+f"((d)[3]) \
        : "r"((a)[0]), "r"((a)[1]), "r"((a)[2]), "r"((a)[3]), "r"((b)[0]), "r"((b)[1]))

__device__ __forceinline__ float warp_red_sum(float v){
#pragma unroll
    for (int o=16;o;o>>=1) v += __shfl_xor_sync(0xffffffffu, v, o);
    return v;
}
__device__ __forceinline__ float warp_red_max(float v){
#pragma unroll
    for (int o=16;o;o>>=1) v = fmaxf(v, __shfl_xor_sync(0xffffffffu, v, o));
    return v;
}
__device__ float block_red_sum(float v, float* sh){
    __syncthreads();
    int lane = threadIdx.x & 31, wid = threadIdx.x >> 5;
    v = warp_red_sum(v);
    if (lane==0) sh[wid] = v;
    __syncthreads();
    int nw = (blockDim.x + 31) >> 5;
    float r = (threadIdx.x < nw) ? sh[threadIdx.x] : 0.f;
    r = warp_red_sum(r);
    if (threadIdx.x==0) sh[0] = r;
    __syncthreads();
    return sh[0];
}
__device__ float block_red_max(float v, float* sh){
    __syncthreads();
    int lane = threadIdx.x & 31, wid = threadIdx.x >> 5;
    v = warp_red_max(v);
    if (lane==0) sh[wid] = v;
    __syncthreads();
    int nw = (blockDim.x + 31) >> 5;
    float r = (threadIdx.x < nw) ? sh[threadIdx.x] : -1e30f;
    r = warp_red_max(r);
    if (threadIdx.x==0) sh[0] = r;
    __syncthreads();
    return sh[0];
}

// ---------------- fused input LN + weight converts (one launch) -------------
// blocks [0,ROWS): LN row; blocks [ROWS, ROWS+320): weight convert (5 x 64 blocks)
__global__ void __launch_bounds__(256) ln_cvt(
    const float* __restrict__ x, const float* __restrict__ lg, const float* __restrict__ lb,
    bf16* __restrict__ xo,
    const float* w0,const float* w1,const float* w2,const float* w3,const float* w4,
    bf16* o0, bf16* o1, bf16* o2, bf16* o3, bf16* o4)
{
    if (blockIdx.x < ROWS){
        __shared__ float sh[33];
        int row = blockIdx.x;
        const float* xr = x + (long)row*DM;
        float v0 = xr[threadIdx.x], v1 = xr[threadIdx.x+256];
        float s  = block_red_sum(v0+v1, sh);
        float s2 = block_red_sum(v0*v0+v1*v1, sh);
        float mu  = s * (1.0f/DM);
        float var = s2 * (1.0f/DM) - mu*mu;
        float inv = rsqrtf(var + EPS);
        bf16* o = xo + (long)row*DM;
        o[threadIdx.x]     = __float2bfloat16((v0-mu)*inv*lg[threadIdx.x]     + lb[threadIdx.x]);
        o[threadIdx.x+256] = __float2bfloat16((v1-mu)*inv*lg[threadIdx.x+256] + lb[threadIdx.x+256]);
    } else {
        int i0 = blockIdx.x - ROWS;
        int wsel = i0 >> 6, blk = i0 & 63;
        const float* w; bf16* o;
        switch (wsel){
            case 0: w=w0; o=o0; break;
            case 1: w=w1; o=o1; break;
            case 2: w=w2; o=o2; break;
            case 3: w=w3; o=o3; break;
            default:w=w4; o=o4; break;
        }
        for (int i = blk*256 + threadIdx.x; i < DM*DM; i += 64*256)
            o[i] = __float2bfloat16(w[i]);
    }
}

// ---------------- fused QKV + tanh-MLP projections, double-buffered ---------
__global__ void __launch_bounds__(256) proj_gemm(
    const bf16* __restrict__ A,
    const bf16* __restrict__ BWq, const bf16* __restrict__ BWk,
    const bf16* __restrict__ BWv, const bf16* __restrict__ BW1,
    bf16* __restrict__ Cq, bf16* __restrict__ Ck, bf16* __restrict__ Cv,
    float* __restrict__ tl, const float* __restrict__ bias,
    const float* __restrict__ w2)
{
    constexpr int BM=128, BN=128, WM=4, WN=2;
    constexpr int WTM=BM/WM, WTN=BN/WN, MF=WTM/16, NF=WTN/8, KS=40;
    __shared__ bf16 sA[2][BM*KS], sB[2][BN*KS];
    const int tid = threadIdx.x, wid = tid>>5, lane = tid&31;
    const int wm = wid%WM, wn = wid/WM, g = lane>>2, tg = lane&3;
    const int z = blockIdx.z;
    const bf16* B = (z==0)?BWq : (z==1)?BWk : (z==2)?BWv : BW1;
    const int m0 = blockIdx.y*BM, n0 = blockIdx.x*BN;

    const int a_r0 = tid>>2,       a_c0 = tid&3;
    const int a_r1 = (tid+256)>>2, a_c1 = (tid+256)&3;

    float acc[MF][NF][4];
#pragma unroll
    for (int i=0;i<MF;i++)
#pragma unroll
        for (int j=0;j<NF;j++)
#pragma unroll
            for (int t=0;t<4;t++) acc[i][j][t]=0.f;

    const int NC = DM>>5;
    *(uint4*)&sA[0][a_r0*KS+a_c0*8] = *(const uint4*)(A+(long)(m0+a_r0)*DM+a_c0*8);
    *(uint4*)&sA[0][a_r1*KS+a_c1*8] = *(const uint4*)(A+(long)(m0+a_r1)*DM+a_c1*8);
    *(uint4*)&sB[0][a_r0*KS+a_c0*8] = *(const uint4*)(B+(long)(n0+a_r0)*DM+a_c0*8);
    *(uint4*)&sB[0][a_r1*KS+a_c1*8] = *(const uint4*)(B+(long)(n0+a_r1)*DM+a_c1*8);
    __syncthreads();

    for (int c=0;c<NC;c++){
        uint4 ra0, ra1, rb0, rb1;
        const bool pf = (c+1 < NC);
        if (pf){
            const int k0n = (c+1)<<5;
            ra0 = *(const uint4*)(A+(long)(m0+a_r0)*DM+k0n+a_c0*8);
            ra1 = *(const uint4*)(A+(long)(m0+a_r1)*DM+k0n+a_c1*8);
            rb0 = *(const uint4*)(B+(long)(n0+a_r0)*DM+k0n+a_c0*8);
            rb1 = *(const uint4*)(B+(long)(n0+a_r1)*DM+k0n+a_c1*8);
        }
        const bf16* pA = sA[c&1]; const bf16* pB = sB[c&1];
#pragma unroll
        for (int ks=0; ks<32; ks+=16){
            const int kr = ks + tg*2;
            uint32_t a[MF][4], b[NF][2];
#pragma unroll
            for (int mf=0;mf<MF;mf++){
                int ar = wm*WTM + mf*16 + g;
                a[mf][0]=*(const uint32_t*)&pA[ ar   *KS+kr  ];
                a[mf][1]=*(const uint32_t*)&pA[(ar+8)*KS+kr  ];
                a[mf][2]=*(const uint32_t*)&pA[ ar   *KS+kr+8];
                a[mf][3]=*(const uint32_t*)&pA[(ar+8)*KS+kr+8];
            }
#pragma unroll
            for (int nf=0;nf<NF;nf++){
                int br = wn*WTN + nf*8 + g;
                b[nf][0]=*(const uint32_t*)&pB[br*KS+kr  ];
                b[nf][1]=*(const uint32_t*)&pB[br*KS+kr+8];
            }
#pragma unroll
            for (int mf=0;mf<MF;mf++)
#pragma unroll
                for (int nf=0;nf<NF;nf++)
                    MMA_BF16(acc[mf][nf], a[mf], b[nf]);
        }
        __syncthreads();
        if (pf){
            bf16* nA = sA[(c+1)&1]; bf16* nB = sB[(c+1)&1];
            *(uint4*)&nA[a_r0*KS+a_c0*8] = ra0;
            *(uint4*)&nA[a_r1*KS+a_c1*8] = ra1;
            *(uint4*)&nB[a_r0*KS+a_c0*8] = rb0;
            *(uint4*)&nB[a_r1*KS+a_c1*8] = rb1;
            __syncthreads();
        }
    }

    if (z==3){
#pragma unroll
        for (int mf=0;mf<MF;mf++){
#pragma unroll
            for (int half=0;half<2;half++){
                int row = m0 + wm*WTM + mf*16 + g + half*8;
                float part = 0.f;
#pragma unroll
                for (int nf=0;nf<NF;nf++){
                    int col = n0 + wn*WTN + nf*8 + tg*2;
                    float v0 = tanhf(acc[mf][nf][half*2+0] + bias[col]);
                    float v1 = tanhf(acc[mf][nf][half*2+1] + bias[col+1]);
                    part += v0*w2[col] + v1*w2[col+1];
                }
                part += __shfl_xor_sync(0xffffffffu, part, 1);
                part += __shfl_xor_sync(0xffffffffu, part, 2);
                if (tg==0) atomicAdd(&tl[row], part);
            }
        }
    } else {
        bf16* Cb = (z==0)?Cq : (z==1)?Ck : Cv;
#pragma unroll
        for (int mf=0;mf<MF;mf++){
#pragma unroll
            for (int half=0;half<2;half++){
                long row = m0 + wm*WTM + mf*16 + g + half*8;
#pragma unroll
                for (int nf=0;nf<NF;nf++){
                    int col = n0 + wn*WTN + nf*8 + tg*2;
                    *(bf162*)(Cb + row*(long)DM + col) =
                        __floats2bfloat162_rn(acc[mf][nf][half*2+0], acc[mf][nf][half*2+1]);
                }
            }
        }
    }
}

// ---------------- Wo GEMM, double-buffered, bf16 out ----------------
__global__ void __launch_bounds__(256) wo_gemm(
    const bf16* __restrict__ A, const bf16* __restrict__ B, bf16* __restrict__ C)
{
    constexpr int BM=128, BN=128, WM=4, WN=2;
    constexpr int WTM=BM/WM, WTN=BN/WN, MF=WTM/16, NF=WTN/8, KS=40;
    __shared__ bf16 sA[2][BM*KS], sB[2][BN*KS];
    const int tid = threadIdx.x, wid = tid>>5, lane = tid&31;
    const int wm = wid%WM, wn = wid/WM, g = lane>>2, tg = lane&3;
    const int m0 = blockIdx.y*BM, n0 = blockIdx.x*BN;

    const int a_r0 = tid>>2,       a_c0 = tid&3;
    const int a_r1 = (tid+256)>>2, a_c1 = (tid+256)&3;

    float acc[MF][NF][4];
#pragma unroll
    for (int i=0;i<MF;i++)
#pragma unroll
        for (int j=0;j<NF;j++)
#pragma unroll
            for (int t=0;t<4;t++) acc[i][j][t]=0.f;

    const int NC = DM>>5;
    *(uint4*)&sA[0][a_r0*KS+a_c0*8] = *(const uint4*)(A+(long)(m0+a_r0)*DM+a_c0*8);
    *(uint4*)&sA[0][a_r1*KS+a_c1*8] = *(const uint4*)(A+(long)(m0+a_r1)*DM+a_c1*8);
    *(uint4*)&sB[0][a_r0*KS+a_c0*8] = *(const uint4*)(B+(long)(n0+a_r0)*DM+a_c0*8);
    *(uint4*)&sB[0][a_r1*KS+a_c1*8] = *(const uint4*)(B+(long)(n0+a_r1)*DM+a_c1*8);
    __syncthreads();

    for (int c=0;c<NC;c++){
        uint4 ra0, ra1, rb0, rb1;
        const bool pf = (c+1 < NC);
        if (pf){
            const int k0n = (c+1)<<5;
            ra0 = *(const uint4*)(A+(long)(m0+a_r0)*DM+k0n+a_c0*8);
            ra1 = *(const uint4*)(A+(long)(m0+a_r1)*DM+k0n+a_c1*8);
            rb0 = *(const uint4*)(B+(long)(n0+a_r0)*DM+k0n+a_c0*8);
            rb1 = *(const uint4*)(B+(long)(n0+a_r1)*DM+k0n+a_c1*8);
        }
        const bf16* pA = sA[c&1]; const bf16* pB = sB[c&1];
#pragma unroll
        for (int ks=0; ks<32; ks+=16){
            const int kr = ks + tg*2;
            uint32_t a[MF][4], b[NF][2];
#pragma unroll
            for (int mf=0;mf<MF;mf++){
                int ar = wm*WTM + mf*16 + g;
                a[mf][0]=*(const uint32_t*)&pA[ ar   *KS+kr  ];
                a[mf][1]=*(const uint32_t*)&pA[(ar+8)*KS+kr  ];
                a[mf][2]=*(const uint32_t*)&pA[ ar   *KS+kr+8];
                a[mf][3]=*(const uint32_t*)&pA[(ar+8)*KS+kr+8];
            }
#pragma unroll
            for (int nf=0;nf<NF;nf++){
                int br = wn*WTN + nf*8 + g;
                b[nf][0]=*(const uint32_t*)&pB[br*KS+kr  ];
                b[nf][1]=*(const uint32_t*)&pB[br*KS+kr+8];
            }
#pragma unroll
            for (int mf=0;mf<MF;mf++)
#pragma unroll
                for (int nf=0;nf<NF;nf++)
                    MMA_BF16(acc[mf][nf], a[mf], b[nf]);
        }
        __syncthreads();
        if (pf){
            bf16* nA = sA[(c+1)&1]; bf16* nB = sB[(c+1)&1];
            *(uint4*)&nA[a_r0*KS+a_c0*8] = ra0;
            *(uint4*)&nA[a_r1*KS+a_c1*8] = ra1;
            *(uint4*)&nB[a_r0*KS+a_c0*8] = rb0;
            *(uint4*)&nB[a_r1*KS+a_c1*8] = rb1;
            __syncthreads();
        }
    }
#pragma unroll
    for (int mf=0;mf<MF;mf++){
#pragma unroll
        for (int half=0;half<2;half++){
            long row = m0 + wm*WTM + mf*16 + g + half*8;
#pragma unroll
            for (int nf=0;nf<NF;nf++){
                int col = n0 + wn*WTN + nf*8 + tg*2;
                *(bf162*)(C + row*(long)DM + col) =
                    __floats2bfloat162_rn(acc[mf][nf][half*2+0], acc[mf][nf][half*2+1]);
            }
        }
    }
}

// ---------------- V transpose, class-permuted ----------------
__global__ void vtrans_p(const bf16* __restrict__ v, bf16* __restrict__ vt){
    __shared__ bf16 t[32][33];
    int z = blockIdx.z, b = z>>3, h = z&7;
    int d = (h<5) ? 1 : (1 << (h-4));
    int Nc = SEQ/d;
    int k0 = blockIdx.x*32, n0 = blockIdx.y*32;
    for (int i = threadIdx.y; i < 32; i += 8)
        t[i][threadIdx.x] = v[(long)(b*SEQ + k0 + i)*DM + h*HD + n0 + threadIdx.x];
    __syncthreads();
    int k = k0 + threadIdx.x;
    int p = (k % d)*Nc + k/d;
    for (int i = threadIdx.y; i < 32; i += 8)
        vt[(long)z*HD*SEQ + (long)(n0+i)*SEQ + p] = t[threadIdx.x][i];
}

// ---------------- unified banded flash attention, cp.async pipelined --------
#define SMEM_ATTN (9216 + 2*18432 + 2*17408)
__global__ void __launch_bounds__(128) uni_attn(
    const bf16* __restrict__ Q, const bf16* __restrict__ K,
    const bf16* __restrict__ Vt, bf16* __restrict__ O)
{
    extern __shared__ char smx[];
    bf16* sQ = (bf16*)smx;

    const int h = blockIdx.y, b = blockIdx.z;
    const int d = (h<5) ? 1 : (1 << (h-4));
    const int w = (h<2) ? SEQ : (h==2) ? 64 : (h==3) ? 128 : (h==4) ? 256 : 64;
    const int Nc = SEQ/d;
    const int cc = blockIdx.x % d;
    const int q0 = (blockIdx.x / d)*64;
    const bool banded = (w < Nc);

    const int tid = threadIdx.x, wp = tid>>5, lane = tid&31;
    const int g = lane>>2, tg = lane&3;

    for (int i = tid; i < 64*8; i += 128){
        int r = i>>3, c = i&7;
        *(uint4*)&sQ[r*72 + c*8] =
            *(const uint4*)(Q + (long)(b*SEQ + cc + (q0+r)*d)*DM + h*HD + c*8);
    }

    float m_run[2] = {-1e30f, -1e30f};
    float l_run[2] = {0.f, 0.f};
    float acc_o[8][4];
#pragma unroll
    for (int i=0;i<8;i++)
#pragma unroll
        for (int t=0;t<4;t++) acc_o[i][t]=0.f;

    const int ar = wp*16 + g;
    const long vbase = (long)(b*8 + h)*HD*SEQ + (long)cc*Nc;

    int nlo = q0 - w; if (nlo < 0) nlo = 0; nlo &= ~127;
    int nhi = q0 + 64 + w; if (nhi > Nc) nhi = Nc;
    const int nt = (nhi - nlo + 127) >> 7;

#define LOAD_TILE(n0_, buf_) do{ \
    bf16* dK = (bf16*)(smx + 9216  + (buf_)*18432); \
    bf16* dV = (bf16*)(smx + 46080 + (buf_)*17408); \
    for (int i = tid; i < 128*8; i += 128){ \
        int r = i>>3, c = i&7; \
        cpa16(&dK[r*72 + c*8], K + (long)(b*SEQ + cc + ((n0_)+r)*d)*DM + h*HD + c*8); } \
    for (int i = tid; i < 64*16; i += 128){ \
        int r = i>>4, c = i&15; \
        cpa16(&dV[r*136 + c*8], Vt + vbase + (long)r*SEQ + (n0_) + c*8); } \
}while(0)

    LOAD_TILE(nlo, 0); CP_COMMIT();

    for (int it = 0; it < nt; it++){
        const int n0 = nlo + it*128;
        if (it+1 < nt){ LOAD_TILE(n0+128, (it+1)&1); CP_COMMIT(); CP_WAIT1(); }
        else CP_WAIT0();
        __syncthreads();
        const bf16* sK = (const bf16*)(smx + 9216  + (it&1)*18432);
        const bf16* sV = (const bf16*)(smx + 46080 + (it&1)*17408);

        float s[16][4];
#pragma unroll
        for (int nf=0;nf<16;nf++)
#pragma unroll
            for (int t=0;t<4;t++) s[nf][t]=0.f;
#pragma unroll
        for (int ks=0; ks<4; ks++){
            const int kr = ks*16 + tg*2;
            uint32_t a[4];
            a[0]=*(const uint32_t*)&sQ[ ar   *72+kr  ];
            a[1]=*(const uint32_t*)&sQ[(ar+8)*72+kr  ];
            a[2]=*(const uint32_t*)&sQ[ ar   *72+kr+8];
            a[3]=*(const uint32_t*)&sQ[(ar+8)*72+kr+8];
#pragma unroll
            for (int nf=0;nf<16;nf++){
                int br = nf*8 + g;
                uint32_t bb[2] = { *(const uint32_t*)&sK[br*72+kr],
                                   *(const uint32_t*)&sK[br*72+kr+8] };
                MMA_BF16(s[nf], a, bb);
            }
        }

        if (banded){
            const int qi0 = q0 + ar, qi1 = qi0 + 8;
#pragma unroll
            for (int nf=0;nf<16;nf++){
                int kj = n0 + nf*8 + tg*2;
                if (abs(qi0 -  kj   ) > w) s[nf][0] = -1e30f;
                if (abs(qi0 - (kj+1)) > w) s[nf][1] = -1e30f;
                if (abs(qi1 -  kj   ) > w) s[nf][2] = -1e30f;
                if (abs(qi1 - (kj+1)) > w) s[nf][3] = -1e30f;
            }
        }

        float ml0=-1e30f, ml1=-1e30f;
#pragma unroll
        for (int nf=0;nf<16;nf++){
            ml0 = fmaxf(ml0, fmaxf(s[nf][0], s[nf][1]));
            ml1 = fmaxf(ml1, fmaxf(s[nf][2], s[nf][3]));
        }
#pragma unroll
        for (int off=1; off<4; off<<=1){
            ml0 = fmaxf(ml0, __shfl_xor_sync(0xffffffffu, ml0, off));
            ml1 = fmaxf(ml1, __shfl_xor_sync(0xffffffffu, ml1, off));
        }
        float mn0 = fmaxf(m_run[0], ml0), mn1 = fmaxf(m_run[1], ml1);
        float c0 = __expf((m_run[0]-mn0)*SCALE), c1 = __expf((m_run[1]-mn1)*SCALE);
        m_run[0]=mn0; m_run[1]=mn1;

        float ps0=0.f, ps1=0.f;
        uint32_t apv[8][4];
#pragma unroll
        for (int kf=0;kf<8;kf++){
            float p00 = __expf((s[2*kf  ][0]-mn0)*SCALE);
            float p01 = __expf((s[2*kf  ][1]-mn0)*SCALE);
            float p02 = __expf((s[2*kf  ][2]-mn1)*SCALE);
            float p03 = __expf((s[2*kf  ][3]-mn1)*SCALE);
            float p10 = __expf((s[2*kf+1][0]-mn0)*SCALE);
            float p11 = __expf((s[2*kf+1][1]-mn0)*SCALE);
            float p12 = __expf((s[2*kf+1][2]-mn1)*SCALE);
            float p13 = __expf((s[2*kf+1][3]-mn1)*SCALE);
            ps0 += p00+p01+p10+p11;
            ps1 += p02+p03+p12+p13;
            bf162 t0 = __floats2bfloat162_rn(p00, p01);
            bf162 t1 = __floats2bfloat162_rn(p02, p03);
            bf162 t2 = __floats2bfloat162_rn(p10, p11);
            bf162 t3 = __floats2bfloat162_rn(p12, p13);
            apv[kf][0] = *(uint32_t*)&t0;
            apv[kf][1] = *(uint32_t*)&t1;
            apv[kf][2] = *(uint32_t*)&t2;
            apv[kf][3] = *(uint32_t*)&t3;
        }
        l_run[0] = l_run[0]*c0 + ps0;
        l_run[1] = l_run[1]*c1 + ps1;
#pragma unroll
        for (int dd=0; dd<8; dd++){
            acc_o[dd][0]*=c0; acc_o[dd][1]*=c0;
            acc_o[dd][2]*=c1; acc_o[dd][3]*=c1;
        }
#pragma unroll
        for (int kf=0;kf<8;kf++){
            const int kr = kf*16 + tg*2;
#pragma unroll
            for (int dd=0; dd<8; dd++){
                int br = dd*8 + g;
                uint32_t bb[2] = { *(const uint32_t*)&sV[br*136+kr],
                                   *(const uint32_t*)&sV[br*136+kr+8] };
                MMA_BF16(acc_o[dd], apv[kf], bb);
            }
        }
        __syncthreads();
    }

    float l0 = l_run[0], l1 = l_run[1];
#pragma unroll
    for (int off=1; off<4; off<<=1){
        l0 += __shfl_xor_sync(0xffffffffu, l0, off);
        l1 += __shfl_xor_sync(0xffffffffu, l1, off);
    }
    float inv0 = 1.0f/l0, inv1 = 1.0f/l1;
    long r0 = (long)(b*SEQ + cc + (q0 + ar    )*d)*DM + h*HD;
    long r1 = (long)(b*SEQ + cc + (q0 + ar + 8)*d)*DM + h*HD;
#pragma unroll
    for (int dd=0; dd<8; dd++){
        int col = dd*8 + tg*2;
        *(bf162*)(O + r0 + col) = __floats2bfloat162_rn(acc_o[dd][0]*inv0, acc_o[dd][1]*inv0);
        *(bf162*)(O + r1 + col) = __floats2bfloat162_rn(acc_o[dd][2]*inv1, acc_o[dd][3]*inv1);
    }
}

// ---------------- T softmax over sequence ----------------
__global__ void tsoftmax_kernel(float* __restrict__ tl){
    __shared__ float sh[33];
    float* p = tl + (long)blockIdx.x*SEQ;
    int tid = threadIdx.x;
    float v0 = p[tid], v1 = p[tid+1024];
    float m = block_red_max(fmaxf(v0,v1), sh);
    float e0 = __expf(v0-m), e1 = __expf(v1-m);
    float s = block_red_sum(e0+e1, sh);
    float inv = 1.0f/s;
    p[tid] = e0*inv; p[tid+1024] = e1*inv;
}

// ---------------- final: gate, residual, output layernorm ----------------
__global__ void __launch_bounds__(128) final_kernel(
    const bf16* __restrict__ proj, const float* __restrict__ x0,
    const float* __restrict__ tl, const float* __restrict__ g,
    const float* __restrict__ b, float* __restrict__ out)
{
    __shared__ float sh[33];
    int row = blockIdx.x;
    float t = tl[row];
    const bf162*  pr = (const bf162*)(proj + (long)row*DM);
    const float2* xr = (const float2*)(x0   + (long)row*DM);
    float2 vv[2];
    float s=0.f, s2=0.f;
#pragma unroll
    for (int i=0;i<2;i++){
        int d2 = threadIdx.x + i*128;
        float2 p = __bfloat1622float2(pr[d2]);
        float2 xx = xr[d2];
        float v0 = p.x*t + xx.x, v1 = p.y*t + xx.y;
        s += v0+v1; s2 += v0*v0+v1*v1;
        vv[i] = make_float2(v0, v1);
    }
    s  = block_red_sum(s,  sh);
    s2 = block_red_sum(s2, sh);
    float mu  = s * (1.0f/DM);
    float var = s2 * (1.0f/DM) - mu*mu;
    float inv = rsqrtf(var + EPS);
    const float2* g2 = (const float2*)g;
    const float2* b2 = (const float2*)b;
    float2* o = (float2*)(out + (long)row*DM);
#pragma unroll
    for (int i=0;i<2;i++){
        int d2 = threadIdx.x + i*128;
        float2 gg = g2[d2], bb = b2[d2];
        o[d2] = make_float2((vv[i].x-mu)*inv*gg.x + bb.x,
                            (vv[i].y-mu)*inv*gg.y + bb.y);
    }
}

// ---------------- launcher ----------------
extern "C" void kernel_launch(void* const* d_in, const int* in_sizes, int n_in,
                              void* d_out, int out_size)
{
    const float* x      = (const float*)d_in[0];
    const float* Wq     = (const float*)d_in[1];
    const float* Wk     = (const float*)d_in[2];
    const float* Wv     = (const float*)d_in[3];
    const float* Wo     = (const float*)d_in[4];
    const float* T_w1   = (const float*)d_in[5];
    const float* T_b1   = (const float*)d_in[6];
    const float* T_w2   = (const float*)d_in[7];
    const float* ln_in_g  = (const float*)d_in[9];
    const float* ln_in_b  = (const float*)d_in[10];
    const float* ln_out_g = (const float*)d_in[11];
    const float* ln_out_b = (const float*)d_in[12];
    float* out = (float*)d_out;

    bf16 *xnh,*qh,*kh,*vh,*ah,*wqh,*wkh,*wvh,*woh,*w1h,*vtp,*projb;
    float *tl;
    cudaGetSymbolAddress((void**)&xnh, g_xnh);
    cudaGetSymbolAddress((void**)&qh,  g_qh);
    cudaGetSymbolAddress((void**)&kh,  g_kh);
    cudaGetSymbolAddress((void**)&vh,  g_vh);
    cudaGetSymbolAddress((void**)&ah,  g_ah);
    cudaGetSymbolAddress((void**)&wqh, g_wqh);
    cudaGetSymbolAddress((void**)&wkh, g_wkh);
    cudaGetSymbolAddress((void**)&wvh, g_wvh);
    cudaGetSymbolAddress((void**)&woh, g_woh);
    cudaGetSymbolAddress((void**)&w1h, g_w1h);
    cudaGetSymbolAddress((void**)&vtp, g_vtp);
    cudaGetSymbolAddress((void**)&projb, g_projb);
    cudaGetSymbolAddress((void**)&tl,  g_tl);

    cudaFuncSetAttribute(uni_attn, cudaFuncAttributeMaxDynamicSharedMemorySize, SMEM_ATTN);

    // 0. zero T-gate accumulators
    cudaMemsetAsync(tl, 0, ROWS*sizeof(float));

    // 1. input LN + weight converts (one launch)
    ln_cvt<<<ROWS+320,256>>>(x, ln_in_g, ln_in_b, xnh,
                             Wq,Wk,Wv,Wo,T_w1, wqh,wkh,wvh,woh,w1h);

    // 2. fused projections + T-gate dot (z=3)
    proj_gemm<<<dim3(DM/128, ROWS/128, 4),256>>>(xnh, wqh,wkh,wvh,w1h,
                                                 qh,kh,vh, tl, T_b1, T_w2);

    // 3. T softmax over sequence (b2 shift cancels)
    tsoftmax_kernel<<<BATCH,1024>>>(tl);

    // 4. all-head attention
    vtrans_p<<<dim3(SEQ/32, HD/32, 16), dim3(32,8)>>>(vh, vtp);
    uni_attn<<<dim3(32, 8, BATCH),128,SMEM_ATTN>>>(qh, kh, vtp, ah);

    // 5. output projection (bf16 out)
    wo_gemm<<<dim3(DM/128, ROWS/128, 1),256>>>(ah, woh, projb);

    // 6. gate * out + residual + output LN
    final_kernel<<<ROWS,128>>>(projb, x, tl, ln_out_g, ln_out_b, out);
}